// round 2
// baseline (speedup 1.0000x reference)
#include <cuda_runtime.h>
#include <cuda_bf16.h>
#include <math.h>

// ---------------- problem constants ----------------
#define BATCH     2
#define HW        128
#define LQ        (HW*HW)          // 16384
#define N_LEVELS  4
#define LIN       (N_LEVELS*LQ)    // 65536
#define D_MODEL   256
#define N_HEADS   8
#define HEAD_DIM  32
#define N_POINTS  4
#define D_FFN     1024
#define LN_EPS    1e-5f

#define M_Q   (BATCH*LQ)           // 32768
#define M_V   (BATCH*LIN)          // 131072

// ---------------- scratch (no allocation allowed) ----------------
// layout (floats):
//   value    [M_V * 256]        @ 0
//   q        [M_Q * 256]        @ 33554432
//   off      [M_Q * 256]        @ 41943040
//   attn     [M_Q * 128]        @ 50331648
//   attnout  [M_Q * 256]        @ 54525952
//   tmp      [M_Q * 256]        @ 62914560
//   src      [M_Q * 256]        @ 71303168
//   h        [M_Q * 1024]       @ 79691776
// total 113246208 floats (~453 MB)
#define OFF_VALUE    0
#define OFF_Q        33554432
#define OFF_OFF      41943040
#define OFF_ATTN     50331648
#define OFF_ATTNOUT  54525952
#define OFF_TMP      62914560
#define OFF_SRC      71303168
#define OFF_H        79691776
#define SCRATCH_FLOATS 113246208

__device__ float g_scratch[SCRATCH_FLOATS];

// ---------------- SGEMM: C[M,N] = epi( (A (+A2)) @ B + bias (, R) ) ----------------
// BM=BN=128, BK=8, TM=TN=8, 256 threads. All dims divisible (M%128==0, N%128==0, K%8==0).
// EPI: 0 = none, 1 = relu, 2 = add residual R
template<bool FUSE_ADD, int EPI>
__global__ void __launch_bounds__(256) sgemm128(
    const float* __restrict__ A, const float* __restrict__ A2,
    const float* __restrict__ B, const float* __restrict__ bias,
    const float* __restrict__ R, float* __restrict__ C,
    int M, int N, int K)
{
    const int BM = 128, BN = 128, BK = 8, TM = 8, TN = 8;
    __shared__ float As[BK][BM];
    __shared__ float Bs[BK][BN];

    const int tid = threadIdx.x;
    const int bm = blockIdx.y, bn = blockIdx.x;

    const int aRow = tid >> 1;            // 0..127
    const int aCol = (tid & 1) * 4;       // 0 or 4
    const int bRow = tid >> 5;            // 0..7
    const int bCol = (tid & 31) * 4;      // 0..124

    const int tRow = (tid >> 4) * TM;     // 0..120
    const int tCol = (tid & 15) * TN;     // 0..120

    const float* Aptr  = A  + (size_t)(bm * BM) * K;
    const float* A2ptr = FUSE_ADD ? (A2 + (size_t)(bm * BM) * K) : nullptr;
    const float* Bptr  = B + bn * BN;

    float acc[TM][TN];
    #pragma unroll
    for (int i = 0; i < TM; i++)
        #pragma unroll
        for (int j = 0; j < TN; j++) acc[i][j] = 0.f;

    for (int k0 = 0; k0 < K; k0 += BK) {
        float4 a = *(const float4*)(Aptr + (size_t)aRow * K + k0 + aCol);
        if (FUSE_ADD) {
            float4 a2 = *(const float4*)(A2ptr + (size_t)aRow * K + k0 + aCol);
            a.x += a2.x; a.y += a2.y; a.z += a2.z; a.w += a2.w;
        }
        As[aCol + 0][aRow] = a.x;
        As[aCol + 1][aRow] = a.y;
        As[aCol + 2][aRow] = a.z;
        As[aCol + 3][aRow] = a.w;

        float4 bv = *(const float4*)(Bptr + (size_t)(k0 + bRow) * N + bCol);
        *(float4*)&Bs[bRow][bCol] = bv;
        __syncthreads();

        #pragma unroll
        for (int k = 0; k < BK; k++) {
            float ra[TM], rb[TN];
            #pragma unroll
            for (int i = 0; i < TM; i++) ra[i] = As[k][tRow + i];
            #pragma unroll
            for (int j = 0; j < TN; j++) rb[j] = Bs[k][tCol + j];
            #pragma unroll
            for (int i = 0; i < TM; i++)
                #pragma unroll
                for (int j = 0; j < TN; j++)
                    acc[i][j] = fmaf(ra[i], rb[j], acc[i][j]);
        }
        __syncthreads();
    }

    const int cRowBase = bm * BM + tRow;
    const int cColBase = bn * BN + tCol;
    #pragma unroll
    for (int i = 0; i < TM; i++) {
        const size_t row = (size_t)(cRowBase + i);
        float* crow = C + row * N + cColBase;
        const float* rrow = (EPI == 2) ? (R + row * N + cColBase) : nullptr;
        #pragma unroll
        for (int j = 0; j < TN; j += 4) {
            float4 v;
            v.x = acc[i][j + 0] + bias[cColBase + j + 0];
            v.y = acc[i][j + 1] + bias[cColBase + j + 1];
            v.z = acc[i][j + 2] + bias[cColBase + j + 2];
            v.w = acc[i][j + 3] + bias[cColBase + j + 3];
            if (EPI == 1) {
                v.x = fmaxf(v.x, 0.f); v.y = fmaxf(v.y, 0.f);
                v.z = fmaxf(v.z, 0.f); v.w = fmaxf(v.w, 0.f);
            }
            if (EPI == 2) {
                float4 r4 = *(const float4*)(rrow + j);
                v.x += r4.x; v.y += r4.y; v.z += r4.z; v.w += r4.w;
            }
            *(float4*)(crow + j) = v;
        }
    }
}

// ---------------- q = cur_src + pos[:, 3] ----------------
__global__ void compute_q_kernel(const float* __restrict__ cur,
                                 const float* __restrict__ pos,
                                 float* __restrict__ q, int total)
{
    int i = blockIdx.x * blockDim.x + threadIdx.x;
    if (i >= total) return;
    int n = i / (LQ * D_MODEL);
    int rem = i - n * (LQ * D_MODEL);
    q[i] = cur[i] + pos[(size_t)(n * N_LEVELS + 3) * (LQ * D_MODEL) + rem];
}

// ---------------- softmax over groups of 16 ----------------
__global__ void softmax16_kernel(float* __restrict__ a, int rows)
{
    int r = blockIdx.x * blockDim.x + threadIdx.x;
    if (r >= rows) return;
    float* p = a + (size_t)r * 16;
    float v[16];
    #pragma unroll
    for (int i = 0; i < 16; i += 4) {
        float4 t = *(const float4*)(p + i);
        v[i] = t.x; v[i+1] = t.y; v[i+2] = t.z; v[i+3] = t.w;
    }
    float mx = v[0];
    #pragma unroll
    for (int i = 1; i < 16; i++) mx = fmaxf(mx, v[i]);
    float s = 0.f;
    #pragma unroll
    for (int i = 0; i < 16; i++) { v[i] = __expf(v[i] - mx); s += v[i]; }
    float inv = 1.f / s;
    #pragma unroll
    for (int i = 0; i < 16; i += 4) {
        float4 t = make_float4(v[i]*inv, v[i+1]*inv, v[i+2]*inv, v[i+3]*inv);
        *(float4*)(p + i) = t;
    }
}

// ---------------- deformable attention gather ----------------
// block = one query (8 warps = 8 heads), lane = head-dim element.
__global__ void __launch_bounds__(256) deform_kernel(
    const float* __restrict__ value,    // (N, LIN, 8, 32)
    const float* __restrict__ off,      // (N*LQ, 256) col = h*32 + l*8 + p*2 + {x,y}
    const float* __restrict__ attnw,    // (N*LQ, 128) col = h*16 + l*4 + p
    const float* __restrict__ ref,      // (N*LQ, 4, 2)
    float* __restrict__ out)            // (N*LQ, 256)
{
    const int q = blockIdx.x;           // 0 .. BATCH*LQ-1
    const int n = q >> 14;              // / LQ
    const int h = threadIdx.x >> 5;
    const int d = threadIdx.x & 31;

    const float* offp = off   + (size_t)q * 256 + h * 32;
    const float* awp  = attnw + (size_t)q * 128 + h * 16;
    const float* refp = ref   + (size_t)q * 8;

    float acc = 0.f;
    #pragma unroll
    for (int l = 0; l < N_LEVELS; l++) {
        const float rx = refp[l * 2 + 0] * 128.f - 0.5f;
        const float ry = refp[l * 2 + 1] * 128.f - 0.5f;
        const float* vb = value + (((size_t)n * LIN + l * LQ) * N_HEADS + h) * HEAD_DIM + d;
        #pragma unroll
        for (int p = 0; p < N_POINTS; p++) {
            const float x = rx + offp[l * 8 + p * 2 + 0];
            const float y = ry + offp[l * 8 + p * 2 + 1];
            const float aw = awp[l * 4 + p];
            const float xf = floorf(x), yf = floorf(y);
            const int x0 = (int)xf, y0 = (int)yf;
            const float wx = x - xf, wy = y - yf;

            const float w00 = (1.f - wx) * (1.f - wy) * aw;
            const float w10 = wx * (1.f - wy) * aw;
            const float w01 = (1.f - wx) * wy * aw;
            const float w11 = wx * wy * aw;

            const bool xin0 = (x0 >= 0) && (x0 < HW);
            const bool xin1 = (x0 + 1 >= 0) && (x0 + 1 < HW);
            const bool yin0 = (y0 >= 0) && (y0 < HW);
            const bool yin1 = (y0 + 1 >= 0) && (y0 + 1 < HW);

            if (xin0 && yin0) acc = fmaf(w00, vb[(size_t)(y0 * HW + x0) * 256], acc);
            if (xin1 && yin0) acc = fmaf(w10, vb[(size_t)(y0 * HW + x0 + 1) * 256], acc);
            if (xin0 && yin1) acc = fmaf(w01, vb[(size_t)((y0 + 1) * HW + x0) * 256], acc);
            if (xin1 && yin1) acc = fmaf(w11, vb[(size_t)((y0 + 1) * HW + x0 + 1) * 256], acc);
        }
    }
    out[(size_t)q * 256 + h * 32 + d] = acc;
}

// ---------------- layernorm over rows of 256 ----------------
// 256 threads = 8 warps, one warp per row; lane handles 8 elements.
__global__ void __launch_bounds__(256) layernorm_kernel(
    const float* __restrict__ X, const float* __restrict__ gamma,
    const float* __restrict__ beta, float* __restrict__ Y, int M)
{
    const int warp = threadIdx.x >> 5;
    const int lane = threadIdx.x & 31;
    const int row = blockIdx.x * 8 + warp;
    if (row >= M) return;

    const float* x = X + (size_t)row * D_MODEL + lane * 8;
    float4 v0 = *(const float4*)(x);
    float4 v1 = *(const float4*)(x + 4);

    float s  = v0.x + v0.y + v0.z + v0.w + v1.x + v1.y + v1.z + v1.w;
    float ss = v0.x*v0.x + v0.y*v0.y + v0.z*v0.z + v0.w*v0.w
             + v1.x*v1.x + v1.y*v1.y + v1.z*v1.z + v1.w*v1.w;
    #pragma unroll
    for (int o = 16; o > 0; o >>= 1) {
        s  += __shfl_xor_sync(0xffffffffu, s,  o);
        ss += __shfl_xor_sync(0xffffffffu, ss, o);
    }
    const float mean = s * (1.f / D_MODEL);
    const float var  = ss * (1.f / D_MODEL) - mean * mean;
    const float rstd = rsqrtf(var + LN_EPS);

    const float* g = gamma + lane * 8;
    const float* b = beta  + lane * 8;
    float4 g0 = *(const float4*)(g);
    float4 g1 = *(const float4*)(g + 4);
    float4 b0 = *(const float4*)(b);
    float4 b1 = *(const float4*)(b + 4);

    float4 o0, o1;
    o0.x = (v0.x - mean) * rstd * g0.x + b0.x;
    o0.y = (v0.y - mean) * rstd * g0.y + b0.y;
    o0.z = (v0.z - mean) * rstd * g0.z + b0.z;
    o0.w = (v0.w - mean) * rstd * g0.w + b0.w;
    o1.x = (v1.x - mean) * rstd * g1.x + b1.x;
    o1.y = (v1.y - mean) * rstd * g1.y + b1.y;
    o1.z = (v1.z - mean) * rstd * g1.z + b1.z;
    o1.w = (v1.w - mean) * rstd * g1.w + b1.w;

    float* y = Y + (size_t)row * D_MODEL + lane * 8;
    *(float4*)(y)     = o0;
    *(float4*)(y + 4) = o1;
}

// ---------------- launch ----------------
extern "C" void kernel_launch(void* const* d_in, const int* in_sizes, int n_in,
                              void* d_out, int out_size)
{
    const float* cur_src = (const float*)d_in[0];
    const float* src_all = (const float*)d_in[1];
    const float* pos     = (const float*)d_in[2];
    const float* ref     = (const float*)d_in[3];
    // d_in[4] spatial_shape, d_in[5] level_start_index: static, unused
    const float* W_off   = (const float*)d_in[6];
    const float* b_off   = (const float*)d_in[7];
    const float* W_attn  = (const float*)d_in[8];
    const float* b_attn  = (const float*)d_in[9];
    const float* W_val   = (const float*)d_in[10];
    const float* b_val   = (const float*)d_in[11];
    const float* W_out   = (const float*)d_in[12];
    const float* b_out   = (const float*)d_in[13];
    const float* gamma1  = (const float*)d_in[14];
    const float* beta1   = (const float*)d_in[15];
    const float* W1      = (const float*)d_in[16];
    const float* b1      = (const float*)d_in[17];
    const float* W2      = (const float*)d_in[18];
    const float* b2      = (const float*)d_in[19];
    const float* gamma2  = (const float*)d_in[20];
    const float* beta2   = (const float*)d_in[21];
    float* out = (float*)d_out;

    float* scratch = nullptr;
    cudaGetSymbolAddress((void**)&scratch, g_scratch);
    float* value   = scratch + OFF_VALUE;
    float* q       = scratch + OFF_Q;
    float* offb    = scratch + OFF_OFF;
    float* attn    = scratch + OFF_ATTN;
    float* attnout = scratch + OFF_ATTNOUT;
    float* tmp     = scratch + OFF_TMP;
    float* src     = scratch + OFF_SRC;
    float* hbuf    = scratch + OFF_H;

    // 1. value = (src_all + pos_flat) @ W_val + b_val   [131072 x 256 x 256]
    {
        dim3 grid(D_MODEL / 128, M_V / 128);
        sgemm128<true, 0><<<grid, 256>>>(src_all, pos, W_val, b_val, nullptr,
                                         value, M_V, D_MODEL, D_MODEL);
    }

    // 2. q = cur_src + pos[:,3]
    {
        int total = M_Q * D_MODEL;
        compute_q_kernel<<<(total + 255) / 256, 256>>>(cur_src, pos, q, total);
    }

    // 3. off = q @ W_off + b_off   [32768 x 256 x 256]
    {
        dim3 grid(256 / 128, M_Q / 128);
        sgemm128<false, 0><<<grid, 256>>>(q, nullptr, W_off, b_off, nullptr,
                                          offb, M_Q, 256, D_MODEL);
    }

    // 4. attn = softmax16( q @ W_attn + b_attn )   [32768 x 128 x 256]
    {
        dim3 grid(128 / 128, M_Q / 128);
        sgemm128<false, 0><<<grid, 256>>>(q, nullptr, W_attn, b_attn, nullptr,
                                          attn, M_Q, 128, D_MODEL);
        int rows = M_Q * N_HEADS;
        softmax16_kernel<<<(rows + 255) / 256, 256>>>(attn, rows);
    }

    // 5. deformable gather -> attnout
    deform_kernel<<<M_Q, 256>>>(value, offb, attn, ref, attnout);

    // 6. tmp = attnout @ W_out + b_out + cur_src ; src = LN1(tmp)
    {
        dim3 grid(D_MODEL / 128, M_Q / 128);
        sgemm128<false, 2><<<grid, 256>>>(attnout, nullptr, W_out, b_out, cur_src,
                                          tmp, M_Q, D_MODEL, D_MODEL);
        layernorm_kernel<<<(M_Q + 7) / 8, 256>>>(tmp, gamma1, beta1, src, M_Q);
    }

    // 7. h = relu(src @ W1 + b1)   [32768 x 1024 x 256]
    {
        dim3 grid(D_FFN / 128, M_Q / 128);
        sgemm128<false, 1><<<grid, 256>>>(src, nullptr, W1, b1, nullptr,
                                          hbuf, M_Q, D_FFN, D_MODEL);
    }

    // 8. tmp = h @ W2 + b2 + src ; out = LN2(tmp)
    {
        dim3 grid(D_MODEL / 128, M_Q / 128);
        sgemm128<false, 2><<<grid, 256>>>(hbuf, nullptr, W2, b2, src,
                                          tmp, M_Q, D_MODEL, D_FFN);
        layernorm_kernel<<<(M_Q + 7) / 8, 256>>>(tmp, gamma2, beta2, out, M_Q);
    }
}

// round 5
// speedup vs baseline: 1.8728x; 1.8728x over previous
#include <cuda_runtime.h>
#include <cuda_bf16.h>
#include <cstdint>
#include <math.h>

// ---------------- problem constants ----------------
#define BATCH     2
#define HW        128
#define LQ        (HW*HW)          // 16384
#define N_LEVELS  4
#define LIN       (N_LEVELS*LQ)    // 65536
#define D_MODEL   256
#define N_HEADS   8
#define HEAD_DIM  32
#define N_POINTS  4
#define D_FFN     1024
#define LN_EPS    1e-5f

#define M_Q   (BATCH*LQ)           // 32768
#define M_V   (BATCH*LIN)          // 131072

// ---------------- scratch ----------------
#define OFF_VALUE    0
#define OFF_Q        33554432
#define OFF_OFF      41943040
#define OFF_ATTN     50331648
#define OFF_ATTNOUT  54525952
#define OFF_TMP      62914560
#define OFF_SRC      71303168
#define OFF_H        79691776
// transposed + hi/lo bf16 split weights, K-major [N,K] (sizes in floats, overallocated)
#define OFF_WVH      113246208
#define OFF_WVL      (OFF_WVH + 65536)
#define OFF_WOH      (OFF_WVL + 65536)
#define OFF_WOL      (OFF_WOH + 65536)
#define OFF_WAH      (OFF_WOL + 65536)
#define OFF_WAL      (OFF_WAH + 32768)
#define OFF_WUH      (OFF_WAL + 32768)
#define OFF_WUL      (OFF_WUH + 65536)
#define OFF_W1H      (OFF_WUL + 65536)
#define OFF_W1L      (OFF_W1H + 262144)
#define OFF_W2H      (OFF_W1L + 262144)
#define OFF_W2L      (OFF_W2H + 262144)
#define SCRATCH_FLOATS (OFF_W2L + 262144)

__device__ float g_scratch[SCRATCH_FLOATS];

// ---------------- helpers ----------------
__device__ __forceinline__ uint32_t smem_u32(const void* p) {
    uint32_t a;
    asm("{ .reg .u64 t; cvta.to.shared.u64 t, %1; cvt.u32.u64 %0, t; }" : "=r"(a) : "l"(p));
    return a;
}

__device__ __forceinline__ void bsplit(float x, unsigned short& h, unsigned short& l) {
    __nv_bfloat16 hb = __float2bfloat16_rn(x);
    __nv_bfloat16 lb = __float2bfloat16_rn(x - __bfloat162float(hb));
    h = __bfloat16_as_ushort(hb);
    l = __bfloat16_as_ushort(lb);
}

__device__ __forceinline__ void ldm_x4(uint32_t* r, uint32_t addr) {
    asm volatile("ldmatrix.sync.aligned.m8n8.x4.shared.b16 {%0,%1,%2,%3}, [%4];"
        : "=r"(r[0]), "=r"(r[1]), "=r"(r[2]), "=r"(r[3]) : "r"(addr));
}

__device__ __forceinline__ void mma_bf16(float* c, const uint32_t* a, const uint32_t* b) {
    asm volatile(
        "mma.sync.aligned.m16n8k16.row.col.f32.bf16.bf16.f32 "
        "{%0,%1,%2,%3}, {%4,%5,%6,%7}, {%8,%9}, {%0,%1,%2,%3};"
        : "+f"(c[0]), "+f"(c[1]), "+f"(c[2]), "+f"(c[3])
        : "r"(a[0]), "r"(a[1]), "r"(a[2]), "r"(a[3]), "r"(b[0]), "r"(b[1]));
}

// ---------------- weight transpose + bf16 hi/lo split ----------------
// W: [K, N] row-major fp32 -> Whi/Wlo: [N, K] K-major bf16
__global__ void wsplit_kernel(const float* __restrict__ W,
                              __nv_bfloat16* __restrict__ Whi,
                              __nv_bfloat16* __restrict__ Wlo,
                              int K, int N) {
    int idx = blockIdx.x * blockDim.x + threadIdx.x;
    if (idx >= K * N) return;
    int k = idx / N, n = idx - k * N;
    float x = W[idx];
    __nv_bfloat16 h = __float2bfloat16_rn(x);
    __nv_bfloat16 l = __float2bfloat16_rn(x - __bfloat162float(h));
    Whi[(size_t)n * K + k] = h;
    Wlo[(size_t)n * K + k] = l;
}

// ---------------- bf16x3 HMMA GEMM ----------------
// C[M,N] = epi( (A (+A2)) @ Wt^T + bias (, R) ), Wt as [N,K] bf16 hi/lo.
// CTA tile 128x128, BK=32, 8 warps (4 m x 2 n), warp tile 32x64.
// EPI: 0 = none, 1 = relu, 2 = + residual R
#define SMPAD 40   // padded row stride in bf16 elems (80 bytes, 16B-aligned, conflict-free)

template<bool FUSE_ADD, int EPI>
__global__ void __launch_bounds__(256, 2) gemm_mma(
    const float* __restrict__ A, const float* __restrict__ A2,
    const __nv_bfloat16* __restrict__ Bhi, const __nv_bfloat16* __restrict__ Blo,
    const float* __restrict__ bias, const float* __restrict__ R,
    float* __restrict__ C, int M, int N, int K)
{
    __shared__ unsigned short sAh[128 * SMPAD];
    __shared__ unsigned short sAl[128 * SMPAD];
    __shared__ unsigned short sBh[128 * SMPAD];
    __shared__ unsigned short sBl[128 * SMPAD];

    const int tid = threadIdx.x;
    const int wid = tid >> 5, lane = tid & 31;
    const int wm = wid & 3, wn = wid >> 2;      // warp grid 4 x 2
    const int m0 = blockIdx.y * 128, n0 = blockIdx.x * 128;

    const float* Arow  = A + (size_t)m0 * K;
    const float* A2row = FUSE_ADD ? (A2 + (size_t)m0 * K) : nullptr;

    // ldmatrix lane addressing components
    const int a_r  = lane & 15;                  // row within 16
    const int a_kb = (lane >> 4) * 16;           // byte col 0/16
    const int b_r  = ((lane >> 4) & 1) * 8 + (lane & 7);
    const int b_kb = ((lane >> 3) & 1) * 16;

    const uint32_t AhB = smem_u32(sAh), AlB = smem_u32(sAl);
    const uint32_t BhB = smem_u32(sBh), BlB = smem_u32(sBl);

    float acc[2][8][4];
    #pragma unroll
    for (int i = 0; i < 2; i++)
        #pragma unroll
        for (int j = 0; j < 8; j++)
            #pragma unroll
            for (int t = 0; t < 4; t++) acc[i][j][t] = 0.f;

    for (int k0 = 0; k0 < K; k0 += 32) {
        // ---- fill SMEM ----
        // A: 128 rows x 32 fp32 -> split -> bf16 hi/lo
        #pragma unroll
        for (int j = 0; j < 4; j++) {
            const int f = tid + j * 256;         // 0..1023
            const int row = f >> 3, c4 = f & 7;  // 8 float4 per row
            const size_t g = (size_t)row * K + k0 + c4 * 4;
            float4 v = *(const float4*)(Arow + g);
            if (FUSE_ADD) {
                float4 v2 = *(const float4*)(A2row + g);
                v.x += v2.x; v.y += v2.y; v.z += v2.z; v.w += v2.w;
            }
            unsigned short h0,h1,h2,h3,l0,l1,l2,l3;
            bsplit(v.x,h0,l0); bsplit(v.y,h1,l1); bsplit(v.z,h2,l2); bsplit(v.w,h3,l3);
            uint2 hp, lp;
            hp.x = ((uint32_t)h1 << 16) | h0;  hp.y = ((uint32_t)h3 << 16) | h2;
            lp.x = ((uint32_t)l1 << 16) | l0;  lp.y = ((uint32_t)l3 << 16) | l2;
            const int so = row * SMPAD + c4 * 4;
            *(uint2*)(sAh + so) = hp;
            *(uint2*)(sAl + so) = lp;
        }
        // B: pre-split bf16, 128 rows x 32 bf16 each of hi/lo = 1024 x 16B chunks
        #pragma unroll
        for (int j = 0; j < 4; j++) {
            const int c = tid + j * 256;         // 0..1023
            const int mat = c >> 9;              // 0 hi, 1 lo
            const int rem = c & 511;
            const int row = rem >> 2, q = rem & 3;
            const __nv_bfloat16* src = (mat ? Blo : Bhi) + (size_t)(n0 + row) * K + k0 + q * 8;
            unsigned short* dst = (mat ? sBl : sBh) + row * SMPAD + q * 8;
            *(uint4*)dst = *(const uint4*)src;
        }
        __syncthreads();

        // ---- compute ----
        #pragma unroll
        for (int ks2 = 0; ks2 <= 32; ks2 += 32) {   // two k16 steps (bytes)
            uint32_t ah[2][4], al[2][4];
            #pragma unroll
            for (int mi = 0; mi < 2; mi++) {
                const uint32_t ao = (uint32_t)((wm * 32 + mi * 16 + a_r) * (SMPAD * 2)) + a_kb + ks2;
                ldm_x4(ah[mi], AhB + ao);
                ldm_x4(al[mi], AlB + ao);
            }
            #pragma unroll
            for (int nc = 0; nc < 4; nc++) {
                uint32_t bh[4], bl[4];
                const uint32_t bo = (uint32_t)((wn * 64 + nc * 16 + b_r) * (SMPAD * 2)) + b_kb + ks2;
                ldm_x4(bh, BhB + bo);
                ldm_x4(bl, BlB + bo);
                #pragma unroll
                for (int mi = 0; mi < 2; mi++) {
                    #pragma unroll
                    for (int s = 0; s < 2; s++) {
                        float* c = acc[mi][nc * 2 + s];
                        mma_bf16(c, ah[mi], bh + s * 2);
                        mma_bf16(c, al[mi], bh + s * 2);
                        mma_bf16(c, ah[mi], bl + s * 2);
                    }
                }
            }
        }
        __syncthreads();
    }

    // ---- epilogue ----
    const int gr = lane >> 2, gc = (lane & 3) * 2;
    #pragma unroll
    for (int mi = 0; mi < 2; mi++) {
        const int row = m0 + wm * 32 + mi * 16 + gr;
        #pragma unroll
        for (int ni = 0; ni < 8; ni++) {
            const int col = n0 + wn * 64 + ni * 8 + gc;
            const float b0 = bias[col], b1 = bias[col + 1];
            float2 v0, v1;
            v0.x = acc[mi][ni][0] + b0; v0.y = acc[mi][ni][1] + b1;
            v1.x = acc[mi][ni][2] + b0; v1.y = acc[mi][ni][3] + b1;
            if (EPI == 1) {
                v0.x = fmaxf(v0.x, 0.f); v0.y = fmaxf(v0.y, 0.f);
                v1.x = fmaxf(v1.x, 0.f); v1.y = fmaxf(v1.y, 0.f);
            }
            if (EPI == 2) {
                float2 r0 = *(const float2*)(R + (size_t)row * N + col);
                float2 r1 = *(const float2*)(R + (size_t)(row + 8) * N + col);
                v0.x += r0.x; v0.y += r0.y; v1.x += r1.x; v1.y += r1.y;
            }
            *(float2*)(C + (size_t)row * N + col) = v0;
            *(float2*)(C + (size_t)(row + 8) * N + col) = v1;
        }
    }
}

// ---------------- q = cur_src + pos[:, 3] ----------------
__global__ void compute_q_kernel(const float* __restrict__ cur,
                                 const float* __restrict__ pos,
                                 float* __restrict__ q, int total)
{
    int i = blockIdx.x * blockDim.x + threadIdx.x;
    if (i >= total) return;
    int n = i / (LQ * D_MODEL);
    int rem = i - n * (LQ * D_MODEL);
    q[i] = cur[i] + pos[(size_t)(n * N_LEVELS + 3) * (LQ * D_MODEL) + rem];
}

// ---------------- softmax over groups of 16 ----------------
__global__ void softmax16_kernel(float* __restrict__ a, int rows)
{
    int r = blockIdx.x * blockDim.x + threadIdx.x;
    if (r >= rows) return;
    float* p = a + (size_t)r * 16;
    float v[16];
    #pragma unroll
    for (int i = 0; i < 16; i += 4) {
        float4 t = *(const float4*)(p + i);
        v[i] = t.x; v[i+1] = t.y; v[i+2] = t.z; v[i+3] = t.w;
    }
    float mx = v[0];
    #pragma unroll
    for (int i = 1; i < 16; i++) mx = fmaxf(mx, v[i]);
    float s = 0.f;
    #pragma unroll
    for (int i = 0; i < 16; i++) { v[i] = __expf(v[i] - mx); s += v[i]; }
    float inv = 1.f / s;
    #pragma unroll
    for (int i = 0; i < 16; i += 4) {
        float4 t = make_float4(v[i]*inv, v[i+1]*inv, v[i+2]*inv, v[i+3]*inv);
        *(float4*)(p + i) = t;
    }
}

// ---------------- deformable attention gather ----------------
__global__ void __launch_bounds__(256) deform_kernel(
    const float* __restrict__ value,
    const float* __restrict__ off,
    const float* __restrict__ attnw,
    const float* __restrict__ ref,
    float* __restrict__ out)
{
    const int q = blockIdx.x;
    const int n = q >> 14;
    const int h = threadIdx.x >> 5;
    const int d = threadIdx.x & 31;

    const float* offp = off   + (size_t)q * 256 + h * 32;
    const float* awp  = attnw + (size_t)q * 128 + h * 16;
    const float* refp = ref   + (size_t)q * 8;

    float acc = 0.f;
    #pragma unroll
    for (int l = 0; l < N_LEVELS; l++) {
        const float rx = refp[l * 2 + 0] * 128.f - 0.5f;
        const float ry = refp[l * 2 + 1] * 128.f - 0.5f;
        const float* vb = value + (((size_t)n * LIN + l * LQ) * N_HEADS + h) * HEAD_DIM + d;
        #pragma unroll
        for (int p = 0; p < N_POINTS; p++) {
            const float x = rx + offp[l * 8 + p * 2 + 0];
            const float y = ry + offp[l * 8 + p * 2 + 1];
            const float aw = awp[l * 4 + p];
            const float xf = floorf(x), yf = floorf(y);
            const int x0 = (int)xf, y0 = (int)yf;
            const float wx = x - xf, wy = y - yf;

            const float w00 = (1.f - wx) * (1.f - wy) * aw;
            const float w10 = wx * (1.f - wy) * aw;
            const float w01 = (1.f - wx) * wy * aw;
            const float w11 = wx * wy * aw;

            const bool xin0 = (x0 >= 0) && (x0 < HW);
            const bool xin1 = (x0 + 1 >= 0) && (x0 + 1 < HW);
            const bool yin0 = (y0 >= 0) && (y0 < HW);
            const bool yin1 = (y0 + 1 >= 0) && (y0 + 1 < HW);

            if (xin0 && yin0) acc = fmaf(w00, vb[(size_t)(y0 * HW + x0) * 256], acc);
            if (xin1 && yin0) acc = fmaf(w10, vb[(size_t)(y0 * HW + x0 + 1) * 256], acc);
            if (xin0 && yin1) acc = fmaf(w01, vb[(size_t)((y0 + 1) * HW + x0) * 256], acc);
            if (xin1 && yin1) acc = fmaf(w11, vb[(size_t)((y0 + 1) * HW + x0 + 1) * 256], acc);
        }
    }
    out[(size_t)q * 256 + h * 32 + d] = acc;
}

// ---------------- layernorm over rows of 256 ----------------
__global__ void __launch_bounds__(256) layernorm_kernel(
    const float* __restrict__ X, const float* __restrict__ gamma,
    const float* __restrict__ beta, float* __restrict__ Y, int M)
{
    const int warp = threadIdx.x >> 5;
    const int lane = threadIdx.x & 31;
    const int row = blockIdx.x * 8 + warp;
    if (row >= M) return;

    const float* x = X + (size_t)row * D_MODEL + lane * 8;
    float4 v0 = *(const float4*)(x);
    float4 v1 = *(const float4*)(x + 4);

    float s  = v0.x + v0.y + v0.z + v0.w + v1.x + v1.y + v1.z + v1.w;
    float ss = v0.x*v0.x + v0.y*v0.y + v0.z*v0.z + v0.w*v0.w
             + v1.x*v1.x + v1.y*v1.y + v1.z*v1.z + v1.w*v1.w;
    #pragma unroll
    for (int o = 16; o > 0; o >>= 1) {
        s  += __shfl_xor_sync(0xffffffffu, s,  o);
        ss += __shfl_xor_sync(0xffffffffu, ss, o);
    }
    const float mean = s * (1.f / D_MODEL);
    const float var  = ss * (1.f / D_MODEL) - mean * mean;
    const float rstd = rsqrtf(var + LN_EPS);

    float4 g0 = *(const float4*)(gamma + lane * 8);
    float4 g1 = *(const float4*)(gamma + lane * 8 + 4);
    float4 b0 = *(const float4*)(beta + lane * 8);
    float4 b1 = *(const float4*)(beta + lane * 8 + 4);

    float4 o0, o1;
    o0.x = (v0.x - mean) * rstd * g0.x + b0.x;
    o0.y = (v0.y - mean) * rstd * g0.y + b0.y;
    o0.z = (v0.z - mean) * rstd * g0.z + b0.z;
    o0.w = (v0.w - mean) * rstd * g0.w + b0.w;
    o1.x = (v1.x - mean) * rstd * g1.x + b1.x;
    o1.y = (v1.y - mean) * rstd * g1.y + b1.y;
    o1.z = (v1.z - mean) * rstd * g1.z + b1.z;
    o1.w = (v1.w - mean) * rstd * g1.w + b1.w;

    float* y = Y + (size_t)row * D_MODEL + lane * 8;
    *(float4*)(y)     = o0;
    *(float4*)(y + 4) = o1;
}

// ---------------- launch ----------------
extern "C" void kernel_launch(void* const* d_in, const int* in_sizes, int n_in,
                              void* d_out, int out_size)
{
    const float* cur_src = (const float*)d_in[0];
    const float* src_all = (const float*)d_in[1];
    const float* pos     = (const float*)d_in[2];
    const float* ref     = (const float*)d_in[3];
    const float* W_off   = (const float*)d_in[6];
    const float* b_off   = (const float*)d_in[7];
    const float* W_attn  = (const float*)d_in[8];
    const float* b_attn  = (const float*)d_in[9];
    const float* W_val   = (const float*)d_in[10];
    const float* b_val   = (const float*)d_in[11];
    const float* W_out   = (const float*)d_in[12];
    const float* b_out   = (const float*)d_in[13];
    const float* gamma1  = (const float*)d_in[14];
    const float* beta1   = (const float*)d_in[15];
    const float* W1      = (const float*)d_in[16];
    const float* b1      = (const float*)d_in[17];
    const float* W2      = (const float*)d_in[18];
    const float* b2      = (const float*)d_in[19];
    const float* gamma2  = (const float*)d_in[20];
    const float* beta2   = (const float*)d_in[21];
    float* out = (float*)d_out;

    float* scratch = nullptr;
    cudaGetSymbolAddress((void**)&scratch, g_scratch);
    float* value   = scratch + OFF_VALUE;
    float* q       = scratch + OFF_Q;
    float* offb    = scratch + OFF_OFF;
    float* attn    = scratch + OFF_ATTN;
    float* attnout = scratch + OFF_ATTNOUT;
    float* tmp     = scratch + OFF_TMP;
    float* src     = scratch + OFF_SRC;
    float* hbuf    = scratch + OFF_H;

    __nv_bfloat16* WVH = (__nv_bfloat16*)(scratch + OFF_WVH);
    __nv_bfloat16* WVL = (__nv_bfloat16*)(scratch + OFF_WVL);
    __nv_bfloat16* WOH = (__nv_bfloat16*)(scratch + OFF_WOH);
    __nv_bfloat16* WOL = (__nv_bfloat16*)(scratch + OFF_WOL);
    __nv_bfloat16* WAH = (__nv_bfloat16*)(scratch + OFF_WAH);
    __nv_bfloat16* WAL = (__nv_bfloat16*)(scratch + OFF_WAL);
    __nv_bfloat16* WUH = (__nv_bfloat16*)(scratch + OFF_WUH);
    __nv_bfloat16* WUL = (__nv_bfloat16*)(scratch + OFF_WUL);
    __nv_bfloat16* W1H = (__nv_bfloat16*)(scratch + OFF_W1H);
    __nv_bfloat16* W1L = (__nv_bfloat16*)(scratch + OFF_W1L);
    __nv_bfloat16* W2H = (__nv_bfloat16*)(scratch + OFF_W2H);
    __nv_bfloat16* W2L = (__nv_bfloat16*)(scratch + OFF_W2L);

    // 0. weight transpose + bf16 split
    wsplit_kernel<<<(256*256 + 255)/256, 256>>>(W_val,  WVH, WVL, 256, 256);
    wsplit_kernel<<<(256*256 + 255)/256, 256>>>(W_off,  WOH, WOL, 256, 256);
    wsplit_kernel<<<(256*128 + 255)/256, 256>>>(W_attn, WAH, WAL, 256, 128);
    wsplit_kernel<<<(256*256 + 255)/256, 256>>>(W_out,  WUH, WUL, 256, 256);
    wsplit_kernel<<<(256*1024 + 255)/256, 256>>>(W1,    W1H, W1L, 256, 1024);
    wsplit_kernel<<<(1024*256 + 255)/256, 256>>>(W2,    W2H, W2L, 1024, 256);

    // 1. value = (src_all + pos_flat) @ W_val + b_val
    {
        dim3 grid(2, M_V / 128);
        gemm_mma<true, 0><<<grid, 256>>>(src_all, pos, WVH, WVL,
                                         b_val, nullptr, value, M_V, 256, 256);
    }

    // 2. q = cur_src + pos[:,3]
    {
        int total = M_Q * D_MODEL;
        compute_q_kernel<<<(total + 255) / 256, 256>>>(cur_src, pos, q, total);
    }

    // 3. off = q @ W_off + b_off
    {
        dim3 grid(2, M_Q / 128);
        gemm_mma<false, 0><<<grid, 256>>>(q, nullptr, WOH, WOL,
                                          b_off, nullptr, offb, M_Q, 256, 256);
    }

    // 4. attn = softmax16( q @ W_attn + b_attn )
    {
        dim3 grid(1, M_Q / 128);
        gemm_mma<false, 0><<<grid, 256>>>(q, nullptr, WAH, WAL,
                                          b_attn, nullptr, attn, M_Q, 128, 256);
        int rows = M_Q * N_HEADS;
        softmax16_kernel<<<(rows + 255) / 256, 256>>>(attn, rows);
    }

    // 5. deformable gather
    deform_kernel<<<M_Q, 256>>>(value, offb, attn, ref, attnout);

    // 6. tmp = attnout @ W_out + b_out + cur_src ; src = LN1(tmp)
    {
        dim3 grid(2, M_Q / 128);
        gemm_mma<false, 2><<<grid, 256>>>(attnout, nullptr, WUH, WUL,
                                          b_out, cur_src, tmp, M_Q, 256, 256);
        layernorm_kernel<<<(M_Q + 7) / 8, 256>>>(tmp, gamma1, beta1, src, M_Q);
    }

    // 7. h = relu(src @ W1 + b1)
    {
        dim3 grid(8, M_Q / 128);
        gemm_mma<false, 1><<<grid, 256>>>(src, nullptr, W1H, W1L,
                                          b1, nullptr, hbuf, M_Q, D_FFN, 256);
    }

    // 8. tmp = h @ W2 + b2 + src ; out = LN2(tmp)
    {
        dim3 grid(2, M_Q / 128);
        gemm_mma<false, 2><<<grid, 256>>>(hbuf, nullptr, W2H, W2L,
                                          b2, src, tmp, M_Q, 256, D_FFN);
        layernorm_kernel<<<(M_Q + 7) / 8, 256>>>(tmp, gamma2, beta2, out, M_Q);
    }
}

// round 6
// speedup vs baseline: 1.9443x; 1.0381x over previous
#include <cuda_runtime.h>
#include <cuda_bf16.h>
#include <cstdint>
#include <math.h>

// ---------------- problem constants ----------------
#define BATCH     2
#define HW        128
#define LQ        (HW*HW)          // 16384
#define N_LEVELS  4
#define LIN       (N_LEVELS*LQ)    // 65536
#define D_MODEL   256
#define N_HEADS   8
#define HEAD_DIM  32
#define N_POINTS  4
#define D_FFN     1024
#define LN_EPS    1e-5f

#define M_Q   (BATCH*LQ)           // 32768
#define M_V   (BATCH*LIN)          // 131072

// ---------------- scratch layout (in floats) ----------------
#define OFF_VALUE   0            // M_V*256 fp32            (33554432)
#define OFF_VAH     33554432     // M_V*256 bf16            (16777216)
#define OFF_VAL     50331648
#define OFF_QH      67108864     // M_Q*256 bf16            (4194304)
#define OFF_QL      71303168
#define OFF_OFFB    75497472     // M_Q*256 fp32            (8388608)
#define OFF_ATTN    83886080     // M_Q*128 fp32            (4194304)
#define OFF_AOH     88080384     // M_Q*256 bf16            (4194304)
#define OFF_AOL     92274688
#define OFF_TMP     96468992     // M_Q*256 fp32            (8388608)
#define OFF_SRC     104857600    // M_Q*256 fp32            (8388608)
#define OFF_SRCH    113246208    // M_Q*256 bf16            (4194304)
#define OFF_SRCL    117440512
#define OFF_HH      121634816    // M_Q*1024 bf16           (16777216)
#define OFF_HL      138412032
#define OFF_WVH     155189248    // 256x256 bf16            (32768)
#define OFF_WVL     155222016
#define OFF_WOH     155254784
#define OFF_WOL     155287552
#define OFF_WAH     155320320    // 128x256 bf16            (16384)
#define OFF_WAL     155336704
#define OFF_WUH     155353088
#define OFF_WUL     155385856
#define OFF_W1H     155418624    // 1024x256 bf16           (131072)
#define OFF_W1L     155549696
#define OFF_W2H     155680768    // 256x1024 bf16           (131072)
#define OFF_W2L     155811840
#define SCRATCH_FLOATS 155942912

__device__ float g_scratch[SCRATCH_FLOATS];

// ---------------- helpers ----------------
__device__ __forceinline__ uint32_t smem_u32(const void* p) {
    uint32_t a;
    asm("{ .reg .u64 t; cvta.to.shared.u64 t, %1; cvt.u32.u64 %0, t; }" : "=r"(a) : "l"(p));
    return a;
}

__device__ __forceinline__ void bsplit(float x, unsigned short& h, unsigned short& l) {
    __nv_bfloat16 hb = __float2bfloat16_rn(x);
    __nv_bfloat16 lb = __float2bfloat16_rn(x - __bfloat162float(hb));
    h = __bfloat16_as_ushort(hb);
    l = __bfloat16_as_ushort(lb);
}

__device__ __forceinline__ void ldm_x4(uint32_t* r, uint32_t addr) {
    asm volatile("ldmatrix.sync.aligned.m8n8.x4.shared.b16 {%0,%1,%2,%3}, [%4];"
        : "=r"(r[0]), "=r"(r[1]), "=r"(r[2]), "=r"(r[3]) : "r"(addr));
}

__device__ __forceinline__ void mma_bf16(float* c, const uint32_t* a, const uint32_t* b) {
    asm volatile(
        "mma.sync.aligned.m16n8k16.row.col.f32.bf16.bf16.f32 "
        "{%0,%1,%2,%3}, {%4,%5,%6,%7}, {%8,%9}, {%0,%1,%2,%3};"
        : "+f"(c[0]), "+f"(c[1]), "+f"(c[2]), "+f"(c[3])
        : "r"(a[0]), "r"(a[1]), "r"(a[2]), "r"(a[3]), "r"(b[0]), "r"(b[1]));
}

__device__ __forceinline__ void cp16(uint32_t dst, const void* src) {
    asm volatile("cp.async.cg.shared.global [%0], [%1], 16;" :: "r"(dst), "l"(src));
}
__device__ __forceinline__ void cp_commit() { asm volatile("cp.async.commit_group;"); }
template<int W> __device__ __forceinline__ void cp_wait() {
    asm volatile("cp.async.wait_group %0;" :: "n"(W));
}

// ---------------- weight transpose + bf16 hi/lo split ----------------
// W: [K, N] row-major fp32 -> Whi/Wlo: [N, K] K-major bf16
__global__ void wsplit_kernel(const float* __restrict__ W,
                              __nv_bfloat16* __restrict__ Whi,
                              __nv_bfloat16* __restrict__ Wlo,
                              int K, int N) {
    int idx = blockIdx.x * blockDim.x + threadIdx.x;
    if (idx >= K * N) return;
    int k = idx / N, n = idx - k * N;
    float x = W[idx];
    __nv_bfloat16 h = __float2bfloat16_rn(x);
    __nv_bfloat16 l = __float2bfloat16_rn(x - __bfloat162float(h));
    Whi[(size_t)n * K + k] = h;
    Wlo[(size_t)n * K + k] = l;
}

// ---------------- elementwise add + bf16 split (equal-shape inputs) ----------------
__global__ void split_add_kernel(const float* __restrict__ a, const float* __restrict__ b,
                                 __nv_bfloat16* __restrict__ oh, __nv_bfloat16* __restrict__ ol,
                                 int total4)
{
    int i = blockIdx.x * blockDim.x + threadIdx.x;
    if (i >= total4) return;
    float4 va = ((const float4*)a)[i];
    float4 vb = ((const float4*)b)[i];
    va.x += vb.x; va.y += vb.y; va.z += vb.z; va.w += vb.w;
    unsigned short h0,h1,h2,h3,l0,l1,l2,l3;
    bsplit(va.x,h0,l0); bsplit(va.y,h1,l1); bsplit(va.z,h2,l2); bsplit(va.w,h3,l3);
    uint2 hp, lp;
    hp.x = ((uint32_t)h1 << 16) | h0;  hp.y = ((uint32_t)h3 << 16) | h2;
    lp.x = ((uint32_t)l1 << 16) | l0;  lp.y = ((uint32_t)l3 << 16) | l2;
    ((uint2*)oh)[i] = hp;
    ((uint2*)ol)[i] = lp;
}

// ---------------- q = cur + pos[:,3] -> bf16 hi/lo ----------------
__global__ void split_q_kernel(const float* __restrict__ cur, const float* __restrict__ pos,
                               __nv_bfloat16* __restrict__ oh, __nv_bfloat16* __restrict__ ol,
                               int total4)
{
    int i = blockIdx.x * blockDim.x + threadIdx.x;
    if (i >= total4) return;
    int idx = i * 4;
    int n = idx / (LQ * D_MODEL);
    int rem = idx - n * (LQ * D_MODEL);
    float4 va = *(const float4*)(cur + idx);
    float4 vb = *(const float4*)(pos + (size_t)(n * N_LEVELS + 3) * (LQ * D_MODEL) + rem);
    va.x += vb.x; va.y += vb.y; va.z += vb.z; va.w += vb.w;
    unsigned short h0,h1,h2,h3,l0,l1,l2,l3;
    bsplit(va.x,h0,l0); bsplit(va.y,h1,l1); bsplit(va.z,h2,l2); bsplit(va.w,h3,l3);
    uint2 hp, lp;
    hp.x = ((uint32_t)h1 << 16) | h0;  hp.y = ((uint32_t)h3 << 16) | h2;
    lp.x = ((uint32_t)l1 << 16) | l0;  lp.y = ((uint32_t)l3 << 16) | l2;
    ((uint2*)oh)[i] = hp;
    ((uint2*)ol)[i] = lp;
}

// ---------------- double-buffered bf16x3 HMMA GEMM ----------------
// C[M,N] = epi( (Ahi+Alo) @ (Bhi+Blo)^T + bias (,R) ), all bf16 pre-split, 3-term MMA.
// CTA tile 128x128, BK=32, 2-stage cp.async pipeline, 8 warps (4m x 2n), warp tile 32x64.
// EPI: 0=none 1=relu 2=+R.  OSPLIT: write Chi/Clo bf16 instead of fp32 C.
#define SMPAD 40                        // padded row stride in bf16 (80B)
#define MATW  (128 * SMPAD)             // ushorts per matrix
#define GEMM_SMEM_BYTES (2 * 4 * MATW * 2)   // 81920

template<int EPI, bool OSPLIT>
__global__ void __launch_bounds__(256, 2) gemm_db(
    const __nv_bfloat16* __restrict__ Ahi, const __nv_bfloat16* __restrict__ Alo,
    const __nv_bfloat16* __restrict__ Bhi, const __nv_bfloat16* __restrict__ Blo,
    const float* __restrict__ bias, const float* __restrict__ R,
    float* __restrict__ C, __nv_bfloat16* __restrict__ Chi, __nv_bfloat16* __restrict__ Clo,
    int M, int N, int K)
{
    extern __shared__ unsigned short sm[];
    const int tid = threadIdx.x;
    const int wid = tid >> 5, lane = tid & 31;
    const int wm = wid & 3, wn = wid >> 2;
    const int m0 = blockIdx.y * 128, n0 = blockIdx.x * 128;
    const uint32_t smb = smem_u32(sm);

    const int a_r  = lane & 15;
    const int a_kb = (lane >> 4) * 16;
    const int b_r  = ((lane >> 4) & 1) * 8 + (lane & 7);
    const int b_kb = ((lane >> 3) & 1) * 16;

    const int row_l = tid >> 2;          // 0..63
    const int q4    = tid & 3;

    float acc[2][8][4];
    #pragma unroll
    for (int i = 0; i < 2; i++)
        #pragma unroll
        for (int j = 0; j < 8; j++)
            #pragma unroll
            for (int t = 0; t < 4; t++) acc[i][j][t] = 0.f;

    const int nchunks = K >> 5;

    auto stage_load = [&](int buf, int k0) {
        #pragma unroll
        for (int j = 0; j < 8; j++) {
            const int mat = j >> 1;                      // 0 Ah 1 Al 2 Bh 3 Bl
            const int row = (j & 1) * 64 + row_l;
            const __nv_bfloat16* base = (mat == 0) ? Ahi : (mat == 1) ? Alo
                                      : (mat == 2) ? Bhi : Blo;
            const int r0 = (mat < 2) ? m0 : n0;
            const __nv_bfloat16* src = base + (size_t)(r0 + row) * K + k0 + q4 * 8;
            const uint32_t dst = smb +
                (uint32_t)(((buf * 4 + mat) * MATW + row * SMPAD + q4 * 8) * 2);
            cp16(dst, src);
        }
        cp_commit();
    };

    stage_load(0, 0);
    for (int i = 0; i < nchunks; i++) {
        if (i + 1 < nchunks) { stage_load((i + 1) & 1, (i + 1) << 5); cp_wait<1>(); }
        else                 { cp_wait<0>(); }
        __syncthreads();

        const uint32_t sb  = smb + (uint32_t)((i & 1) * 4 * MATW * 2);
        const uint32_t AhB = sb,               AlB = sb + MATW * 2;
        const uint32_t BhB = sb + 2 * MATW * 2, BlB = sb + 3 * MATW * 2;

        #pragma unroll
        for (int ks2 = 0; ks2 <= 32; ks2 += 32) {        // two k16 steps (byte offset)
            uint32_t ah[2][4], al[2][4];
            #pragma unroll
            for (int mi = 0; mi < 2; mi++) {
                const uint32_t ao = (uint32_t)((wm * 32 + mi * 16 + a_r) * (SMPAD * 2)) + a_kb + ks2;
                ldm_x4(ah[mi], AhB + ao);
                ldm_x4(al[mi], AlB + ao);
            }
            #pragma unroll
            for (int nc = 0; nc < 4; nc++) {
                uint32_t bh[4], bl[4];
                const uint32_t bo = (uint32_t)((wn * 64 + nc * 16 + b_r) * (SMPAD * 2)) + b_kb + ks2;
                ldm_x4(bh, BhB + bo);
                ldm_x4(bl, BlB + bo);
                #pragma unroll
                for (int mi = 0; mi < 2; mi++) {
                    #pragma unroll
                    for (int s = 0; s < 2; s++) {
                        float* c = acc[mi][nc * 2 + s];
                        mma_bf16(c, ah[mi], bh + s * 2);
                        mma_bf16(c, al[mi], bh + s * 2);
                        mma_bf16(c, ah[mi], bl + s * 2);
                    }
                }
            }
        }
        __syncthreads();
    }

    // ---- epilogue ----
    const int gr = lane >> 2, gc = (lane & 3) * 2;
    #pragma unroll
    for (int mi = 0; mi < 2; mi++) {
        const int row = m0 + wm * 32 + mi * 16 + gr;
        #pragma unroll
        for (int ni = 0; ni < 8; ni++) {
            const int col = n0 + wn * 64 + ni * 8 + gc;
            const float b0 = bias[col], b1 = bias[col + 1];
            float2 v0, v1;
            v0.x = acc[mi][ni][0] + b0; v0.y = acc[mi][ni][1] + b1;
            v1.x = acc[mi][ni][2] + b0; v1.y = acc[mi][ni][3] + b1;
            if (EPI == 1) {
                v0.x = fmaxf(v0.x, 0.f); v0.y = fmaxf(v0.y, 0.f);
                v1.x = fmaxf(v1.x, 0.f); v1.y = fmaxf(v1.y, 0.f);
            }
            if (EPI == 2) {
                float2 r0 = *(const float2*)(R + (size_t)row * N + col);
                float2 r1 = *(const float2*)(R + (size_t)(row + 8) * N + col);
                v0.x += r0.x; v0.y += r0.y; v1.x += r1.x; v1.y += r1.y;
            }
            if (OSPLIT) {
                unsigned short h0,h1,l0,l1,h2,h3,l2,l3;
                bsplit(v0.x,h0,l0); bsplit(v0.y,h1,l1);
                bsplit(v1.x,h2,l2); bsplit(v1.y,h3,l3);
                *(uint32_t*)(Chi + (size_t)row * N + col)       = ((uint32_t)h1 << 16) | h0;
                *(uint32_t*)(Clo + (size_t)row * N + col)       = ((uint32_t)l1 << 16) | l0;
                *(uint32_t*)(Chi + (size_t)(row + 8) * N + col) = ((uint32_t)h3 << 16) | h2;
                *(uint32_t*)(Clo + (size_t)(row + 8) * N + col) = ((uint32_t)l3 << 16) | l2;
            } else {
                *(float2*)(C + (size_t)row * N + col) = v0;
                *(float2*)(C + (size_t)(row + 8) * N + col) = v1;
            }
        }
    }
}

// ---------------- softmax over groups of 16 ----------------
__global__ void softmax16_kernel(float* __restrict__ a, int rows)
{
    int r = blockIdx.x * blockDim.x + threadIdx.x;
    if (r >= rows) return;
    float* p = a + (size_t)r * 16;
    float v[16];
    #pragma unroll
    for (int i = 0; i < 16; i += 4) {
        float4 t = *(const float4*)(p + i);
        v[i] = t.x; v[i+1] = t.y; v[i+2] = t.z; v[i+3] = t.w;
    }
    float mx = v[0];
    #pragma unroll
    for (int i = 1; i < 16; i++) mx = fmaxf(mx, v[i]);
    float s = 0.f;
    #pragma unroll
    for (int i = 0; i < 16; i++) { v[i] = __expf(v[i] - mx); s += v[i]; }
    float inv = 1.f / s;
    #pragma unroll
    for (int i = 0; i < 16; i += 4) {
        float4 t = make_float4(v[i]*inv, v[i+1]*inv, v[i+2]*inv, v[i+3]*inv);
        *(float4*)(p + i) = t;
    }
}

// ---------------- deformable attention gather (bf16 split output) ----------------
__global__ void __launch_bounds__(256) deform_kernel(
    const float* __restrict__ value,
    const float* __restrict__ off,
    const float* __restrict__ attnw,
    const float* __restrict__ ref,
    __nv_bfloat16* __restrict__ outh,
    __nv_bfloat16* __restrict__ outl)
{
    const int q = blockIdx.x;
    const int n = q >> 14;
    const int h = threadIdx.x >> 5;
    const int d = threadIdx.x & 31;

    const float* offp = off   + (size_t)q * 256 + h * 32;
    const float* awp  = attnw + (size_t)q * 128 + h * 16;
    const float* refp = ref   + (size_t)q * 8;

    float acc = 0.f;
    #pragma unroll
    for (int l = 0; l < N_LEVELS; l++) {
        const float rx = refp[l * 2 + 0] * 128.f - 0.5f;
        const float ry = refp[l * 2 + 1] * 128.f - 0.5f;
        const float* vb = value + (((size_t)n * LIN + l * LQ) * N_HEADS + h) * HEAD_DIM + d;
        #pragma unroll
        for (int p = 0; p < N_POINTS; p++) {
            const float x = rx + offp[l * 8 + p * 2 + 0];
            const float y = ry + offp[l * 8 + p * 2 + 1];
            const float aw = awp[l * 4 + p];
            const float xf = floorf(x), yf = floorf(y);
            const int x0 = (int)xf, y0 = (int)yf;
            const float wx = x - xf, wy = y - yf;

            const float w00 = (1.f - wx) * (1.f - wy) * aw;
            const float w10 = wx * (1.f - wy) * aw;
            const float w01 = (1.f - wx) * wy * aw;
            const float w11 = wx * wy * aw;

            const bool xin0 = (x0 >= 0) && (x0 < HW);
            const bool xin1 = (x0 + 1 >= 0) && (x0 + 1 < HW);
            const bool yin0 = (y0 >= 0) && (y0 < HW);
            const bool yin1 = (y0 + 1 >= 0) && (y0 + 1 < HW);

            if (xin0 && yin0) acc = fmaf(w00, vb[(size_t)(y0 * HW + x0) * 256], acc);
            if (xin1 && yin0) acc = fmaf(w10, vb[(size_t)(y0 * HW + x0 + 1) * 256], acc);
            if (xin0 && yin1) acc = fmaf(w01, vb[(size_t)((y0 + 1) * HW + x0) * 256], acc);
            if (xin1 && yin1) acc = fmaf(w11, vb[(size_t)((y0 + 1) * HW + x0 + 1) * 256], acc);
        }
    }
    unsigned short hb, lb;
    bsplit(acc, hb, lb);
    outh[(size_t)q * 256 + h * 32 + d] = __ushort_as_bfloat16(hb);
    outl[(size_t)q * 256 + h * 32 + d] = __ushort_as_bfloat16(lb);
}

// ---------------- layernorm over rows of 256 (optional split copy) ----------------
template<bool OSPLIT>
__global__ void __launch_bounds__(256) layernorm_kernel(
    const float* __restrict__ X, const float* __restrict__ gamma,
    const float* __restrict__ beta, float* __restrict__ Y,
    __nv_bfloat16* __restrict__ Yh, __nv_bfloat16* __restrict__ Yl, int M)
{
    const int warp = threadIdx.x >> 5;
    const int lane = threadIdx.x & 31;
    const int row = blockIdx.x * 8 + warp;
    if (row >= M) return;

    const float* x = X + (size_t)row * D_MODEL + lane * 8;
    float4 v0 = *(const float4*)(x);
    float4 v1 = *(const float4*)(x + 4);

    float s  = v0.x + v0.y + v0.z + v0.w + v1.x + v1.y + v1.z + v1.w;
    float ss = v0.x*v0.x + v0.y*v0.y + v0.z*v0.z + v0.w*v0.w
             + v1.x*v1.x + v1.y*v1.y + v1.z*v1.z + v1.w*v1.w;
    #pragma unroll
    for (int o = 16; o > 0; o >>= 1) {
        s  += __shfl_xor_sync(0xffffffffu, s,  o);
        ss += __shfl_xor_sync(0xffffffffu, ss, o);
    }
    const float mean = s * (1.f / D_MODEL);
    const float var  = ss * (1.f / D_MODEL) - mean * mean;
    const float rstd = rsqrtf(var + LN_EPS);

    float4 g0 = *(const float4*)(gamma + lane * 8);
    float4 g1 = *(const float4*)(gamma + lane * 8 + 4);
    float4 b0 = *(const float4*)(beta + lane * 8);
    float4 b1 = *(const float4*)(beta + lane * 8 + 4);

    float4 o0, o1;
    o0.x = (v0.x - mean) * rstd * g0.x + b0.x;
    o0.y = (v0.y - mean) * rstd * g0.y + b0.y;
    o0.z = (v0.z - mean) * rstd * g0.z + b0.z;
    o0.w = (v0.w - mean) * rstd * g0.w + b0.w;
    o1.x = (v1.x - mean) * rstd * g1.x + b1.x;
    o1.y = (v1.y - mean) * rstd * g1.y + b1.y;
    o1.z = (v1.z - mean) * rstd * g1.z + b1.z;
    o1.w = (v1.w - mean) * rstd * g1.w + b1.w;

    float* y = Y + (size_t)row * D_MODEL + lane * 8;
    *(float4*)(y)     = o0;
    *(float4*)(y + 4) = o1;

    if (OSPLIT) {
        const float vals[8] = {o0.x,o0.y,o0.z,o0.w,o1.x,o1.y,o1.z,o1.w};
        unsigned short hh[8], ll[8];
        #pragma unroll
        for (int i = 0; i < 8; i++) bsplit(vals[i], hh[i], ll[i]);
        uint4 hp, lp;
        hp.x = ((uint32_t)hh[1]<<16)|hh[0]; hp.y = ((uint32_t)hh[3]<<16)|hh[2];
        hp.z = ((uint32_t)hh[5]<<16)|hh[4]; hp.w = ((uint32_t)hh[7]<<16)|hh[6];
        lp.x = ((uint32_t)ll[1]<<16)|ll[0]; lp.y = ((uint32_t)ll[3]<<16)|ll[2];
        lp.z = ((uint32_t)ll[5]<<16)|ll[4]; lp.w = ((uint32_t)ll[7]<<16)|ll[6];
        *(uint4*)(Yh + (size_t)row * D_MODEL + lane * 8) = hp;
        *(uint4*)(Yl + (size_t)row * D_MODEL + lane * 8) = lp;
    }
}

// ---------------- launch ----------------
extern "C" void kernel_launch(void* const* d_in, const int* in_sizes, int n_in,
                              void* d_out, int out_size)
{
    const float* cur_src = (const float*)d_in[0];
    const float* src_all = (const float*)d_in[1];
    const float* pos     = (const float*)d_in[2];
    const float* ref     = (const float*)d_in[3];
    const float* W_off   = (const float*)d_in[6];
    const float* b_off   = (const float*)d_in[7];
    const float* W_attn  = (const float*)d_in[8];
    const float* b_attn  = (const float*)d_in[9];
    const float* W_val   = (const float*)d_in[10];
    const float* b_val   = (const float*)d_in[11];
    const float* W_out   = (const float*)d_in[12];
    const float* b_out   = (const float*)d_in[13];
    const float* gamma1  = (const float*)d_in[14];
    const float* beta1   = (const float*)d_in[15];
    const float* W1      = (const float*)d_in[16];
    const float* b1      = (const float*)d_in[17];
    const float* W2      = (const float*)d_in[18];
    const float* b2      = (const float*)d_in[19];
    const float* gamma2  = (const float*)d_in[20];
    const float* beta2   = (const float*)d_in[21];
    float* out = (float*)d_out;

    float* scratch = nullptr;
    cudaGetSymbolAddress((void**)&scratch, g_scratch);
    float* value   = scratch + OFF_VALUE;
    float* offb    = scratch + OFF_OFFB;
    float* attn    = scratch + OFF_ATTN;
    float* tmp     = scratch + OFF_TMP;
    float* src     = scratch + OFF_SRC;

    __nv_bfloat16* VAH = (__nv_bfloat16*)(scratch + OFF_VAH);
    __nv_bfloat16* VAL = (__nv_bfloat16*)(scratch + OFF_VAL);
    __nv_bfloat16* QH  = (__nv_bfloat16*)(scratch + OFF_QH);
    __nv_bfloat16* QL  = (__nv_bfloat16*)(scratch + OFF_QL);
    __nv_bfloat16* AOH = (__nv_bfloat16*)(scratch + OFF_AOH);
    __nv_bfloat16* AOL = (__nv_bfloat16*)(scratch + OFF_AOL);
    __nv_bfloat16* SRCH= (__nv_bfloat16*)(scratch + OFF_SRCH);
    __nv_bfloat16* SRCL= (__nv_bfloat16*)(scratch + OFF_SRCL);
    __nv_bfloat16* HH  = (__nv_bfloat16*)(scratch + OFF_HH);
    __nv_bfloat16* HL  = (__nv_bfloat16*)(scratch + OFF_HL);
    __nv_bfloat16* WVH = (__nv_bfloat16*)(scratch + OFF_WVH);
    __nv_bfloat16* WVL = (__nv_bfloat16*)(scratch + OFF_WVL);
    __nv_bfloat16* WOH = (__nv_bfloat16*)(scratch + OFF_WOH);
    __nv_bfloat16* WOL = (__nv_bfloat16*)(scratch + OFF_WOL);
    __nv_bfloat16* WAH = (__nv_bfloat16*)(scratch + OFF_WAH);
    __nv_bfloat16* WAL = (__nv_bfloat16*)(scratch + OFF_WAL);
    __nv_bfloat16* WUH = (__nv_bfloat16*)(scratch + OFF_WUH);
    __nv_bfloat16* WUL = (__nv_bfloat16*)(scratch + OFF_WUL);
    __nv_bfloat16* W1H = (__nv_bfloat16*)(scratch + OFF_W1H);
    __nv_bfloat16* W1L = (__nv_bfloat16*)(scratch + OFF_W1L);
    __nv_bfloat16* W2H = (__nv_bfloat16*)(scratch + OFF_W2H);
    __nv_bfloat16* W2L = (__nv_bfloat16*)(scratch + OFF_W2L);

    cudaFuncSetAttribute((const void*)gemm_db<0, false>,
                         cudaFuncAttributeMaxDynamicSharedMemorySize, GEMM_SMEM_BYTES);
    cudaFuncSetAttribute((const void*)gemm_db<1, true>,
                         cudaFuncAttributeMaxDynamicSharedMemorySize, GEMM_SMEM_BYTES);
    cudaFuncSetAttribute((const void*)gemm_db<2, false>,
                         cudaFuncAttributeMaxDynamicSharedMemorySize, GEMM_SMEM_BYTES);

    // 0. weight transpose + bf16 split
    wsplit_kernel<<<(256*256 + 255)/256, 256>>>(W_val,  WVH, WVL, 256, 256);
    wsplit_kernel<<<(256*256 + 255)/256, 256>>>(W_off,  WOH, WOL, 256, 256);
    wsplit_kernel<<<(256*128 + 255)/256, 256>>>(W_attn, WAH, WAL, 256, 128);
    wsplit_kernel<<<(256*256 + 255)/256, 256>>>(W_out,  WUH, WUL, 256, 256);
    wsplit_kernel<<<(256*1024 + 255)/256, 256>>>(W1,    W1H, W1L, 256, 1024);
    wsplit_kernel<<<(1024*256 + 255)/256, 256>>>(W2,    W2H, W2L, 1024, 256);

    // 0b. activation presplits
    split_add_kernel<<<(M_V*64 + 255)/256, 256>>>(src_all, pos, VAH, VAL, M_V * 64);
    split_q_kernel<<<(M_Q*64 + 255)/256, 256>>>(cur_src, pos, QH, QL, M_Q * 64);

    // 1. value = (src_all + pos) @ W_val + b_val
    {
        dim3 grid(2, M_V / 128);
        gemm_db<0, false><<<grid, 256, GEMM_SMEM_BYTES>>>(
            VAH, VAL, WVH, WVL, b_val, nullptr, value, nullptr, nullptr, M_V, 256, 256);
    }

    // 3. off = q @ W_off + b_off
    {
        dim3 grid(2, M_Q / 128);
        gemm_db<0, false><<<grid, 256, GEMM_SMEM_BYTES>>>(
            QH, QL, WOH, WOL, b_off, nullptr, offb, nullptr, nullptr, M_Q, 256, 256);
    }

    // 4. attn = softmax16( q @ W_attn + b_attn )
    {
        dim3 grid(1, M_Q / 128);
        gemm_db<0, false><<<grid, 256, GEMM_SMEM_BYTES>>>(
            QH, QL, WAH, WAL, b_attn, nullptr, attn, nullptr, nullptr, M_Q, 128, 256);
        int rows = M_Q * N_HEADS;
        softmax16_kernel<<<(rows + 255) / 256, 256>>>(attn, rows);
    }

    // 5. deformable gather -> bf16 split attnout
    deform_kernel<<<M_Q, 256>>>(value, offb, attn, ref, AOH, AOL);

    // 6. tmp = attnout @ W_out + b_out + cur_src ; src = LN1(tmp) (+ split copy)
    {
        dim3 grid(2, M_Q / 128);
        gemm_db<2, false><<<grid, 256, GEMM_SMEM_BYTES>>>(
            AOH, AOL, WUH, WUL, b_out, cur_src, tmp, nullptr, nullptr, M_Q, 256, 256);
        layernorm_kernel<true><<<(M_Q + 7) / 8, 256>>>(tmp, gamma1, beta1, src, SRCH, SRCL, M_Q);
    }

    // 7. h = relu(src @ W1 + b1) -> bf16 split
    {
        dim3 grid(8, M_Q / 128);
        gemm_db<1, true><<<grid, 256, GEMM_SMEM_BYTES>>>(
            SRCH, SRCL, W1H, W1L, b1, nullptr, nullptr, HH, HL, M_Q, D_FFN, 256);
    }

    // 8. tmp = h @ W2 + b2 + src ; out = LN2(tmp)
    {
        dim3 grid(2, M_Q / 128);
        gemm_db<2, false><<<grid, 256, GEMM_SMEM_BYTES>>>(
            HH, HL, W2H, W2L, b2, src, tmp, nullptr, nullptr, M_Q, 256, D_FFN);
        layernorm_kernel<false><<<(M_Q + 7) / 8, 256>>>(tmp, gamma2, beta2, out, nullptr, nullptr, M_Q);
    }
}

// round 7
// speedup vs baseline: 2.3719x; 1.2199x over previous
#include <cuda_runtime.h>
#include <cuda_bf16.h>
#include <cstdint>
#include <math.h>

// ---------------- problem constants ----------------
#define BATCH     2
#define HW        128
#define LQ        (HW*HW)          // 16384
#define N_LEVELS  4
#define LIN       (N_LEVELS*LQ)    // 65536
#define D_MODEL   256
#define N_HEADS   8
#define HEAD_DIM  32
#define N_POINTS  4
#define D_FFN     1024
#define LN_EPS    1e-5f

#define M_Q   (BATCH*LQ)           // 32768
#define M_V   (BATCH*LIN)          // 131072

// ---------------- scratch layout (in floats) ----------------
#define OFF_VAB     0            // (src_all+pos) bf16   M_V*256   -> 16777216 fl
#define OFF_VALUEB  16777216     // value bf16           M_V*256   -> 16777216 fl
#define OFF_QB      33554432     // q bf16               M_Q*256   -> 4194304 fl
#define OFF_OFFB    37748736     // off fp32             M_Q*256   -> 8388608 fl
#define OFF_ATTN    46137344     // attn fp32            M_Q*128   -> 4194304 fl
#define OFF_AOB     50331648     // attnout bf16         M_Q*256   -> 4194304 fl
#define OFF_TMP     54525952     // fp32                 M_Q*256   -> 8388608 fl
#define OFF_SRC     62914560     // fp32                 M_Q*256   -> 8388608 fl
#define OFF_SRCB    71303168     // src bf16             M_Q*256   -> 4194304 fl
#define OFF_HB      75497472     // h bf16               M_Q*1024  -> 16777216 fl
#define OFF_WVH     92274688     // 256x256 bf16 -> 32768 fl each
#define OFF_WVL     92307456
#define OFF_WOH     92340224
#define OFF_WOL     92372992
#define OFF_WAH     92405760     // 128x256 bf16 -> 16384 fl each
#define OFF_WAL     92422144
#define OFF_WUH     92438528
#define OFF_WUL     92471296
#define OFF_W1H     92504064     // 1024x256 bf16 -> 131072 fl each
#define OFF_W1L     92635136
#define OFF_W2H     92766208     // 256x1024 bf16
#define OFF_W2L     92897280
#define SCRATCH_FLOATS 93028352

__device__ float g_scratch[SCRATCH_FLOATS];

// ---------------- helpers ----------------
__device__ __forceinline__ uint32_t smem_u32(const void* p) {
    uint32_t a;
    asm("{ .reg .u64 t; cvta.to.shared.u64 t, %1; cvt.u32.u64 %0, t; }" : "=r"(a) : "l"(p));
    return a;
}

__device__ __forceinline__ void bsplit(float x, unsigned short& h, unsigned short& l) {
    __nv_bfloat16 hb = __float2bfloat16_rn(x);
    __nv_bfloat16 lb = __float2bfloat16_rn(x - __bfloat162float(hb));
    h = __bfloat16_as_ushort(hb);
    l = __bfloat16_as_ushort(lb);
}

__device__ __forceinline__ unsigned short b16(float x) {
    return __bfloat16_as_ushort(__float2bfloat16_rn(x));
}

__device__ __forceinline__ void ldm_x4(uint32_t* r, uint32_t addr) {
    asm volatile("ldmatrix.sync.aligned.m8n8.x4.shared.b16 {%0,%1,%2,%3}, [%4];"
        : "=r"(r[0]), "=r"(r[1]), "=r"(r[2]), "=r"(r[3]) : "r"(addr));
}

__device__ __forceinline__ void mma_bf16(float* c, const uint32_t* a, const uint32_t* b) {
    asm volatile(
        "mma.sync.aligned.m16n8k16.row.col.f32.bf16.bf16.f32 "
        "{%0,%1,%2,%3}, {%4,%5,%6,%7}, {%8,%9}, {%0,%1,%2,%3};"
        : "+f"(c[0]), "+f"(c[1]), "+f"(c[2]), "+f"(c[3])
        : "r"(a[0]), "r"(a[1]), "r"(a[2]), "r"(a[3]), "r"(b[0]), "r"(b[1]));
}

__device__ __forceinline__ void cp16(uint32_t dst, const void* src) {
    asm volatile("cp.async.cg.shared.global [%0], [%1], 16;" :: "r"(dst), "l"(src));
}
__device__ __forceinline__ void cp_commit() { asm volatile("cp.async.commit_group;"); }
template<int W> __device__ __forceinline__ void cp_wait() {
    asm volatile("cp.async.wait_group %0;" :: "n"(W));
}

// ---------------- merged weight transpose + bf16 hi/lo split ----------------
struct WSJobs {
    const float* src[6];
    __nv_bfloat16* hi[6];
    __nv_bfloat16* lo[6];
    int K[6];
    int N[6];
    int off[7];
};

__global__ void wsplit_all_kernel(WSJobs jobs)
{
    int idx = blockIdx.x * blockDim.x + threadIdx.x;
    if (idx >= jobs.off[6]) return;
    #pragma unroll
    for (int s = 0; s < 6; s++) {
        if (idx >= jobs.off[s] && idx < jobs.off[s + 1]) {
            int local = idx - jobs.off[s];
            int N = jobs.N[s], K = jobs.K[s];
            int k = local / N, n = local - k * N;
            float x = jobs.src[s][local];
            __nv_bfloat16 h = __float2bfloat16_rn(x);
            __nv_bfloat16 l = __float2bfloat16_rn(x - __bfloat162float(h));
            jobs.hi[s][(size_t)n * K + k] = h;
            jobs.lo[s][(size_t)n * K + k] = l;
            return;
        }
    }
}

// ---------------- elementwise add -> single bf16 ----------------
__global__ void add_cvt_kernel(const float* __restrict__ a, const float* __restrict__ b,
                               __nv_bfloat16* __restrict__ o, int total4)
{
    int i = blockIdx.x * blockDim.x + threadIdx.x;
    if (i >= total4) return;
    float4 va = ((const float4*)a)[i];
    float4 vb = ((const float4*)b)[i];
    uint2 hp;
    hp.x = ((uint32_t)b16(va.y + vb.y) << 16) | b16(va.x + vb.x);
    hp.y = ((uint32_t)b16(va.w + vb.w) << 16) | b16(va.z + vb.z);
    ((uint2*)o)[i] = hp;
}

// ---------------- q = cur + pos[:,3] -> single bf16 ----------------
__global__ void q_cvt_kernel(const float* __restrict__ cur, const float* __restrict__ pos,
                             __nv_bfloat16* __restrict__ o, int total4)
{
    int i = blockIdx.x * blockDim.x + threadIdx.x;
    if (i >= total4) return;
    int idx = i * 4;
    int n = idx / (LQ * D_MODEL);
    int rem = idx - n * (LQ * D_MODEL);
    float4 va = *(const float4*)(cur + idx);
    float4 vb = *(const float4*)(pos + (size_t)(n * N_LEVELS + 3) * (LQ * D_MODEL) + rem);
    uint2 hp;
    hp.x = ((uint32_t)b16(va.y + vb.y) << 16) | b16(va.x + vb.x);
    hp.y = ((uint32_t)b16(va.w + vb.w) << 16) | b16(va.z + vb.z);
    ((uint2*)o)[i] = hp;
}

// ---------------- 2-term bf16 HMMA GEMM ----------------
// C = epi( A @ (Bhi+Blo)^T + bias (,R) ); A single bf16, B pre-split hi/lo [N,K].
// CTA tile 128x128, BK=32, 2-stage cp.async double buffer, 8 warps (4m x 2n).
// EPI: 0=none 1=relu 2=+R.  OMODE: 0=fp32 C, 1=bf16 Cb.
#define SMPAD 40
#define MATW  (128 * SMPAD)
#define GEMM_SMEM_BYTES (2 * 3 * MATW * 2)   // 61440

template<int EPI, int OMODE>
__global__ void __launch_bounds__(256, 2) gemm2(
    const __nv_bfloat16* __restrict__ A,
    const __nv_bfloat16* __restrict__ Bhi, const __nv_bfloat16* __restrict__ Blo,
    const float* __restrict__ bias, const float* __restrict__ R,
    float* __restrict__ C, __nv_bfloat16* __restrict__ Cb,
    int M, int N, int K)
{
    extern __shared__ unsigned short sm[];
    const int tid = threadIdx.x;
    const int wid = tid >> 5, lane = tid & 31;
    const int wm = wid & 3, wn = wid >> 2;
    const int m0 = blockIdx.y * 128, n0 = blockIdx.x * 128;
    const uint32_t smb = smem_u32(sm);

    const int a_r  = lane & 15;
    const int a_kb = (lane >> 4) * 16;
    const int b_r  = ((lane >> 4) & 1) * 8 + (lane & 7);
    const int b_kb = ((lane >> 3) & 1) * 16;

    const int row_l = tid >> 2;          // 0..63
    const int q4    = tid & 3;

    float acc[2][8][4];
    #pragma unroll
    for (int i = 0; i < 2; i++)
        #pragma unroll
        for (int j = 0; j < 8; j++)
            #pragma unroll
            for (int t = 0; t < 4; t++) acc[i][j][t] = 0.f;

    const int nchunks = K >> 5;

    auto stage_load = [&](int buf, int k0) {
        #pragma unroll
        for (int j = 0; j < 6; j++) {
            const int mat = j >> 1;                     // 0 A, 1 Bh, 2 Bl
            const int row = (j & 1) * 64 + row_l;
            const __nv_bfloat16* base = (mat == 0) ? A : (mat == 1) ? Bhi : Blo;
            const int r0 = (mat == 0) ? m0 : n0;
            const __nv_bfloat16* src = base + (size_t)(r0 + row) * K + k0 + q4 * 8;
            const uint32_t dst = smb +
                (uint32_t)(((buf * 3 + mat) * MATW + row * SMPAD + q4 * 8) * 2);
            cp16(dst, src);
        }
        cp_commit();
    };

    stage_load(0, 0);
    for (int i = 0; i < nchunks; i++) {
        if (i + 1 < nchunks) { stage_load((i + 1) & 1, (i + 1) << 5); cp_wait<1>(); }
        else                 { cp_wait<0>(); }
        __syncthreads();

        const uint32_t sb  = smb + (uint32_t)((i & 1) * 3 * MATW * 2);
        const uint32_t AB  = sb;
        const uint32_t BhB = sb + MATW * 2, BlB = sb + 2 * MATW * 2;

        #pragma unroll
        for (int ks2 = 0; ks2 <= 32; ks2 += 32) {
            uint32_t ar[2][4];
            #pragma unroll
            for (int mi = 0; mi < 2; mi++) {
                const uint32_t ao = (uint32_t)((wm * 32 + mi * 16 + a_r) * (SMPAD * 2)) + a_kb + ks2;
                ldm_x4(ar[mi], AB + ao);
            }
            #pragma unroll
            for (int nc = 0; nc < 4; nc++) {
                uint32_t bh[4], bl[4];
                const uint32_t bo = (uint32_t)((wn * 64 + nc * 16 + b_r) * (SMPAD * 2)) + b_kb + ks2;
                ldm_x4(bh, BhB + bo);
                ldm_x4(bl, BlB + bo);
                #pragma unroll
                for (int mi = 0; mi < 2; mi++) {
                    #pragma unroll
                    for (int s = 0; s < 2; s++) {
                        float* c = acc[mi][nc * 2 + s];
                        mma_bf16(c, ar[mi], bh + s * 2);
                        mma_bf16(c, ar[mi], bl + s * 2);
                    }
                }
            }
        }
        __syncthreads();
    }

    // ---- epilogue ----
    const int gr = lane >> 2, gc = (lane & 3) * 2;
    #pragma unroll
    for (int mi = 0; mi < 2; mi++) {
        const int row = m0 + wm * 32 + mi * 16 + gr;
        #pragma unroll
        for (int ni = 0; ni < 8; ni++) {
            const int col = n0 + wn * 64 + ni * 8 + gc;
            const float b0 = bias[col], b1 = bias[col + 1];
            float2 v0, v1;
            v0.x = acc[mi][ni][0] + b0; v0.y = acc[mi][ni][1] + b1;
            v1.x = acc[mi][ni][2] + b0; v1.y = acc[mi][ni][3] + b1;
            if (EPI == 1) {
                v0.x = fmaxf(v0.x, 0.f); v0.y = fmaxf(v0.y, 0.f);
                v1.x = fmaxf(v1.x, 0.f); v1.y = fmaxf(v1.y, 0.f);
            }
            if (EPI == 2) {
                float2 r0 = *(const float2*)(R + (size_t)row * N + col);
                float2 r1 = *(const float2*)(R + (size_t)(row + 8) * N + col);
                v0.x += r0.x; v0.y += r0.y; v1.x += r1.x; v1.y += r1.y;
            }
            if (OMODE == 1) {
                *(uint32_t*)(Cb + (size_t)row * N + col) =
                    ((uint32_t)b16(v0.y) << 16) | b16(v0.x);
                *(uint32_t*)(Cb + (size_t)(row + 8) * N + col) =
                    ((uint32_t)b16(v1.y) << 16) | b16(v1.x);
            } else {
                *(float2*)(C + (size_t)row * N + col) = v0;
                *(float2*)(C + (size_t)(row + 8) * N + col) = v1;
            }
        }
    }
}

// ---------------- softmax over groups of 16 ----------------
__global__ void softmax16_kernel(float* __restrict__ a, int rows)
{
    int r = blockIdx.x * blockDim.x + threadIdx.x;
    if (r >= rows) return;
    float* p = a + (size_t)r * 16;
    float v[16];
    #pragma unroll
    for (int i = 0; i < 16; i += 4) {
        float4 t = *(const float4*)(p + i);
        v[i] = t.x; v[i+1] = t.y; v[i+2] = t.z; v[i+3] = t.w;
    }
    float mx = v[0];
    #pragma unroll
    for (int i = 1; i < 16; i++) mx = fmaxf(mx, v[i]);
    float s = 0.f;
    #pragma unroll
    for (int i = 0; i < 16; i++) { v[i] = __expf(v[i] - mx); s += v[i]; }
    float inv = 1.f / s;
    #pragma unroll
    for (int i = 0; i < 16; i += 4) {
        float4 t = make_float4(v[i]*inv, v[i+1]*inv, v[i+2]*inv, v[i+3]*inv);
        *(float4*)(p + i) = t;
    }
}

// ---------------- deformable gather (bf16 value, bf16 out) ----------------
__global__ void __launch_bounds__(256) deform_kernel(
    const __nv_bfloat16* __restrict__ value,
    const float* __restrict__ off,
    const float* __restrict__ attnw,
    const float* __restrict__ ref,
    __nv_bfloat16* __restrict__ outb)
{
    const int q = blockIdx.x;
    const int n = q >> 14;
    const int h = threadIdx.x >> 5;
    const int d = threadIdx.x & 31;

    const float* offp = off   + (size_t)q * 256 + h * 32;
    const float* awp  = attnw + (size_t)q * 128 + h * 16;
    const float* refp = ref   + (size_t)q * 8;

    float acc = 0.f;
    #pragma unroll
    for (int l = 0; l < N_LEVELS; l++) {
        const float rx = refp[l * 2 + 0] * 128.f - 0.5f;
        const float ry = refp[l * 2 + 1] * 128.f - 0.5f;
        const __nv_bfloat16* vb = value + (((size_t)n * LIN + l * LQ) * N_HEADS + h) * HEAD_DIM + d;
        #pragma unroll
        for (int p = 0; p < N_POINTS; p++) {
            const float x = rx + offp[l * 8 + p * 2 + 0];
            const float y = ry + offp[l * 8 + p * 2 + 1];
            const float aw = awp[l * 4 + p];
            const float xf = floorf(x), yf = floorf(y);
            const int x0 = (int)xf, y0 = (int)yf;
            const float wx = x - xf, wy = y - yf;

            const float w00 = (1.f - wx) * (1.f - wy) * aw;
            const float w10 = wx * (1.f - wy) * aw;
            const float w01 = (1.f - wx) * wy * aw;
            const float w11 = wx * wy * aw;

            const bool xin0 = (x0 >= 0) && (x0 < HW);
            const bool xin1 = (x0 + 1 >= 0) && (x0 + 1 < HW);
            const bool yin0 = (y0 >= 0) && (y0 < HW);
            const bool yin1 = (y0 + 1 >= 0) && (y0 + 1 < HW);

            if (xin0 && yin0) acc = fmaf(w00, __bfloat162float(vb[(size_t)(y0 * HW + x0) * 256]), acc);
            if (xin1 && yin0) acc = fmaf(w10, __bfloat162float(vb[(size_t)(y0 * HW + x0 + 1) * 256]), acc);
            if (xin0 && yin1) acc = fmaf(w01, __bfloat162float(vb[(size_t)((y0 + 1) * HW + x0) * 256]), acc);
            if (xin1 && yin1) acc = fmaf(w11, __bfloat162float(vb[(size_t)((y0 + 1) * HW + x0 + 1) * 256]), acc);
        }
    }
    outb[(size_t)q * 256 + h * 32 + d] = __float2bfloat16_rn(acc);
}

// ---------------- layernorm (optional single-bf16 copy) ----------------
template<bool OB>
__global__ void __launch_bounds__(256) layernorm_kernel(
    const float* __restrict__ X, const float* __restrict__ gamma,
    const float* __restrict__ beta, float* __restrict__ Y,
    __nv_bfloat16* __restrict__ Yb, int M)
{
    const int warp = threadIdx.x >> 5;
    const int lane = threadIdx.x & 31;
    const int row = blockIdx.x * 8 + warp;
    if (row >= M) return;

    const float* x = X + (size_t)row * D_MODEL + lane * 8;
    float4 v0 = *(const float4*)(x);
    float4 v1 = *(const float4*)(x + 4);

    float s  = v0.x + v0.y + v0.z + v0.w + v1.x + v1.y + v1.z + v1.w;
    float ss = v0.x*v0.x + v0.y*v0.y + v0.z*v0.z + v0.w*v0.w
             + v1.x*v1.x + v1.y*v1.y + v1.z*v1.z + v1.w*v1.w;
    #pragma unroll
    for (int o = 16; o > 0; o >>= 1) {
        s  += __shfl_xor_sync(0xffffffffu, s,  o);
        ss += __shfl_xor_sync(0xffffffffu, ss, o);
    }
    const float mean = s * (1.f / D_MODEL);
    const float var  = ss * (1.f / D_MODEL) - mean * mean;
    const float rstd = rsqrtf(var + LN_EPS);

    float4 g0 = *(const float4*)(gamma + lane * 8);
    float4 g1 = *(const float4*)(gamma + lane * 8 + 4);
    float4 b0 = *(const float4*)(beta + lane * 8);
    float4 b1 = *(const float4*)(beta + lane * 8 + 4);

    float4 o0, o1;
    o0.x = (v0.x - mean) * rstd * g0.x + b0.x;
    o0.y = (v0.y - mean) * rstd * g0.y + b0.y;
    o0.z = (v0.z - mean) * rstd * g0.z + b0.z;
    o0.w = (v0.w - mean) * rstd * g0.w + b0.w;
    o1.x = (v1.x - mean) * rstd * g1.x + b1.x;
    o1.y = (v1.y - mean) * rstd * g1.y + b1.y;
    o1.z = (v1.z - mean) * rstd * g1.z + b1.z;
    o1.w = (v1.w - mean) * rstd * g1.w + b1.w;

    float* y = Y + (size_t)row * D_MODEL + lane * 8;
    *(float4*)(y)     = o0;
    *(float4*)(y + 4) = o1;

    if (OB) {
        uint4 hp;
        hp.x = ((uint32_t)b16(o0.y) << 16) | b16(o0.x);
        hp.y = ((uint32_t)b16(o0.w) << 16) | b16(o0.z);
        hp.z = ((uint32_t)b16(o1.y) << 16) | b16(o1.x);
        hp.w = ((uint32_t)b16(o1.w) << 16) | b16(o1.z);
        *(uint4*)(Yb + (size_t)row * D_MODEL + lane * 8) = hp;
    }
}

// ---------------- launch ----------------
extern "C" void kernel_launch(void* const* d_in, const int* in_sizes, int n_in,
                              void* d_out, int out_size)
{
    const float* cur_src = (const float*)d_in[0];
    const float* src_all = (const float*)d_in[1];
    const float* pos     = (const float*)d_in[2];
    const float* ref     = (const float*)d_in[3];
    const float* W_off   = (const float*)d_in[6];
    const float* b_off   = (const float*)d_in[7];
    const float* W_attn  = (const float*)d_in[8];
    const float* b_attn  = (const float*)d_in[9];
    const float* W_val   = (const float*)d_in[10];
    const float* b_val   = (const float*)d_in[11];
    const float* W_out   = (const float*)d_in[12];
    const float* b_out   = (const float*)d_in[13];
    const float* gamma1  = (const float*)d_in[14];
    const float* beta1   = (const float*)d_in[15];
    const float* W1      = (const float*)d_in[16];
    const float* b1      = (const float*)d_in[17];
    const float* W2      = (const float*)d_in[18];
    const float* b2      = (const float*)d_in[19];
    const float* gamma2  = (const float*)d_in[20];
    const float* beta2   = (const float*)d_in[21];
    float* out = (float*)d_out;

    float* scratch = nullptr;
    cudaGetSymbolAddress((void**)&scratch, g_scratch);
    float* offb = scratch + OFF_OFFB;
    float* attn = scratch + OFF_ATTN;
    float* tmp  = scratch + OFF_TMP;
    float* src  = scratch + OFF_SRC;

    __nv_bfloat16* VAB = (__nv_bfloat16*)(scratch + OFF_VAB);
    __nv_bfloat16* VALB= (__nv_bfloat16*)(scratch + OFF_VALUEB);
    __nv_bfloat16* QB  = (__nv_bfloat16*)(scratch + OFF_QB);
    __nv_bfloat16* AOB = (__nv_bfloat16*)(scratch + OFF_AOB);
    __nv_bfloat16* SRCB= (__nv_bfloat16*)(scratch + OFF_SRCB);
    __nv_bfloat16* HB  = (__nv_bfloat16*)(scratch + OFF_HB);
    __nv_bfloat16* WVH = (__nv_bfloat16*)(scratch + OFF_WVH);
    __nv_bfloat16* WVL = (__nv_bfloat16*)(scratch + OFF_WVL);
    __nv_bfloat16* WOH = (__nv_bfloat16*)(scratch + OFF_WOH);
    __nv_bfloat16* WOL = (__nv_bfloat16*)(scratch + OFF_WOL);
    __nv_bfloat16* WAH = (__nv_bfloat16*)(scratch + OFF_WAH);
    __nv_bfloat16* WAL = (__nv_bfloat16*)(scratch + OFF_WAL);
    __nv_bfloat16* WUH = (__nv_bfloat16*)(scratch + OFF_WUH);
    __nv_bfloat16* WUL = (__nv_bfloat16*)(scratch + OFF_WUL);
    __nv_bfloat16* W1H = (__nv_bfloat16*)(scratch + OFF_W1H);
    __nv_bfloat16* W1L = (__nv_bfloat16*)(scratch + OFF_W1L);
    __nv_bfloat16* W2H = (__nv_bfloat16*)(scratch + OFF_W2H);
    __nv_bfloat16* W2L = (__nv_bfloat16*)(scratch + OFF_W2L);

    cudaFuncSetAttribute((const void*)gemm2<0, 0>,
                         cudaFuncAttributeMaxDynamicSharedMemorySize, GEMM_SMEM_BYTES);
    cudaFuncSetAttribute((const void*)gemm2<0, 1>,
                         cudaFuncAttributeMaxDynamicSharedMemorySize, GEMM_SMEM_BYTES);
    cudaFuncSetAttribute((const void*)gemm2<1, 1>,
                         cudaFuncAttributeMaxDynamicSharedMemorySize, GEMM_SMEM_BYTES);
    cudaFuncSetAttribute((const void*)gemm2<2, 0>,
                         cudaFuncAttributeMaxDynamicSharedMemorySize, GEMM_SMEM_BYTES);

    // 0. merged weight transpose + split (1 launch)
    {
        WSJobs j;
        j.src[0] = W_val;  j.hi[0] = WVH; j.lo[0] = WVL; j.K[0] = 256;  j.N[0] = 256;
        j.src[1] = W_off;  j.hi[1] = WOH; j.lo[1] = WOL; j.K[1] = 256;  j.N[1] = 256;
        j.src[2] = W_attn; j.hi[2] = WAH; j.lo[2] = WAL; j.K[2] = 256;  j.N[2] = 128;
        j.src[3] = W_out;  j.hi[3] = WUH; j.lo[3] = WUL; j.K[3] = 256;  j.N[3] = 256;
        j.src[4] = W1;     j.hi[4] = W1H; j.lo[4] = W1L; j.K[4] = 256;  j.N[4] = 1024;
        j.src[5] = W2;     j.hi[5] = W2H; j.lo[5] = W2L; j.K[5] = 1024; j.N[5] = 256;
        int off = 0;
        for (int s = 0; s < 6; s++) { j.off[s] = off; off += j.K[s] * j.N[s]; }
        j.off[6] = off;
        wsplit_all_kernel<<<(off + 255) / 256, 256>>>(j);
    }

    // 0b. activation converts
    add_cvt_kernel<<<(M_V*64 + 255)/256, 256>>>(src_all, pos, VAB, M_V * 64);
    q_cvt_kernel<<<(M_Q*64 + 255)/256, 256>>>(cur_src, pos, QB, M_Q * 64);

    // 1. value = (src_all + pos) @ W_val + b_val  -> bf16
    {
        dim3 grid(2, M_V / 128);
        gemm2<0, 1><<<grid, 256, GEMM_SMEM_BYTES>>>(
            VAB, WVH, WVL, b_val, nullptr, nullptr, VALB, M_V, 256, 256);
    }

    // 2. off = q @ W_off + b_off  -> fp32
    {
        dim3 grid(2, M_Q / 128);
        gemm2<0, 0><<<grid, 256, GEMM_SMEM_BYTES>>>(
            QB, WOH, WOL, b_off, nullptr, offb, nullptr, M_Q, 256, 256);
    }

    // 3. attn = softmax16( q @ W_attn + b_attn )
    {
        dim3 grid(1, M_Q / 128);
        gemm2<0, 0><<<grid, 256, GEMM_SMEM_BYTES>>>(
            QB, WAH, WAL, b_attn, nullptr, attn, nullptr, M_Q, 128, 256);
        int rows = M_Q * N_HEADS;
        softmax16_kernel<<<(rows + 255) / 256, 256>>>(attn, rows);
    }

    // 4. deformable gather -> bf16 attnout
    deform_kernel<<<M_Q, 256>>>(VALB, offb, attn, ref, AOB);

    // 5. tmp = attnout @ W_out + b_out + cur_src ; src = LN1(tmp) (+ bf16 copy)
    {
        dim3 grid(2, M_Q / 128);
        gemm2<2, 0><<<grid, 256, GEMM_SMEM_BYTES>>>(
            AOB, WUH, WUL, b_out, cur_src, tmp, nullptr, M_Q, 256, 256);
        layernorm_kernel<true><<<(M_Q + 7) / 8, 256>>>(tmp, gamma1, beta1, src, SRCB, M_Q);
    }

    // 6. h = relu(src @ W1 + b1) -> bf16
    {
        dim3 grid(8, M_Q / 128);
        gemm2<1, 1><<<grid, 256, GEMM_SMEM_BYTES>>>(
            SRCB, W1H, W1L, b1, nullptr, nullptr, HB, M_Q, D_FFN, 256);
    }

    // 7. tmp = h @ W2 + b2 + src ; out = LN2(tmp)
    {
        dim3 grid(2, M_Q / 128);
        gemm2<2, 0><<<grid, 256, GEMM_SMEM_BYTES>>>(
            HB, W2H, W2L, b2, src, tmp, nullptr, M_Q, 256, D_FFN);
        layernorm_kernel<false><<<(M_Q + 7) / 8, 256>>>(tmp, gamma2, beta2, out, nullptr, M_Q);
    }
}

// round 8
// speedup vs baseline: 2.5195x; 1.0623x over previous
#include <cuda_runtime.h>
#include <cuda_bf16.h>
#include <cstdint>
#include <math.h>

// ---------------- problem constants ----------------
#define BATCH     2
#define HW        128
#define LQ        (HW*HW)          // 16384
#define N_LEVELS  4
#define LIN       (N_LEVELS*LQ)    // 65536
#define D_MODEL   256
#define N_HEADS   8
#define HEAD_DIM  32
#define N_POINTS  4
#define D_FFN     1024
#define LN_EPS    1e-5f

#define M_Q   (BATCH*LQ)           // 32768
#define M_V   (BATCH*LIN)          // 131072

// ---------------- scratch layout (in floats) ----------------
#define OFF_VAB     0            // (src_all+pos) bf16   M_V*256
#define OFF_VALUEB  16777216     // value bf16           M_V*256
#define OFF_QB      33554432     // q bf16               M_Q*256
#define OFF_OFFB    37748736     // off fp32             M_Q*256
#define OFF_ATTN    46137344     // attn fp32            M_Q*128
#define OFF_AOB     50331648     // attnout bf16         M_Q*256
#define OFF_TMP     54525952     // fp32                 M_Q*256
#define OFF_SRC     62914560     // fp32                 M_Q*256
#define OFF_SRCB    71303168     // src bf16             M_Q*256
#define OFF_HB      75497472     // h bf16               M_Q*1024
#define OFF_WVH     92274688
#define OFF_WVL     92307456
#define OFF_WOH     92340224
#define OFF_WOL     92372992
#define OFF_WAH     92405760
#define OFF_WAL     92422144
#define OFF_WUH     92438528
#define OFF_WUL     92471296
#define OFF_W1H     92504064
#define OFF_W1L     92635136
#define OFF_W2H     92766208
#define OFF_W2L     92897280
#define SCRATCH_FLOATS 93028352

__device__ float g_scratch[SCRATCH_FLOATS];

// ---------------- helpers ----------------
__device__ __forceinline__ uint32_t smem_u32(const void* p) {
    uint32_t a;
    asm("{ .reg .u64 t; cvta.to.shared.u64 t, %1; cvt.u32.u64 %0, t; }" : "=r"(a) : "l"(p));
    return a;
}

__device__ __forceinline__ unsigned short b16(float x) {
    return __bfloat16_as_ushort(__float2bfloat16_rn(x));
}

__device__ __forceinline__ void ldm_x4(uint32_t* r, uint32_t addr) {
    asm volatile("ldmatrix.sync.aligned.m8n8.x4.shared.b16 {%0,%1,%2,%3}, [%4];"
        : "=r"(r[0]), "=r"(r[1]), "=r"(r[2]), "=r"(r[3]) : "r"(addr));
}

__device__ __forceinline__ void mma_bf16(float* c, const uint32_t* a, const uint32_t* b) {
    asm volatile(
        "mma.sync.aligned.m16n8k16.row.col.f32.bf16.bf16.f32 "
        "{%0,%1,%2,%3}, {%4,%5,%6,%7}, {%8,%9}, {%0,%1,%2,%3};"
        : "+f"(c[0]), "+f"(c[1]), "+f"(c[2]), "+f"(c[3])
        : "r"(a[0]), "r"(a[1]), "r"(a[2]), "r"(a[3]), "r"(b[0]), "r"(b[1]));
}

__device__ __forceinline__ void cp16(uint32_t dst, const void* src) {
    asm volatile("cp.async.cg.shared.global [%0], [%1], 16;" :: "r"(dst), "l"(src));
}
__device__ __forceinline__ void cp_commit() { asm volatile("cp.async.commit_group;"); }
template<int W> __device__ __forceinline__ void cp_wait() {
    asm volatile("cp.async.wait_group %0;" :: "n"(W));
}

// ---------------- merged weight transpose + bf16 hi/lo split ----------------
struct WSJobs {
    const float* src[6];
    __nv_bfloat16* hi[6];
    __nv_bfloat16* lo[6];
    int K[6];
    int N[6];
    int off[7];
};

__global__ void wsplit_all_kernel(WSJobs jobs)
{
    int idx = blockIdx.x * blockDim.x + threadIdx.x;
    if (idx >= jobs.off[6]) return;
    #pragma unroll
    for (int s = 0; s < 6; s++) {
        if (idx >= jobs.off[s] && idx < jobs.off[s + 1]) {
            int local = idx - jobs.off[s];
            int N = jobs.N[s], K = jobs.K[s];
            int k = local / N, n = local - k * N;
            float x = jobs.src[s][local];
            __nv_bfloat16 h = __float2bfloat16_rn(x);
            __nv_bfloat16 l = __float2bfloat16_rn(x - __bfloat162float(h));
            jobs.hi[s][(size_t)n * K + k] = h;
            jobs.lo[s][(size_t)n * K + k] = l;
            return;
        }
    }
}

// ---------------- elementwise add -> single bf16 ----------------
__global__ void add_cvt_kernel(const float* __restrict__ a, const float* __restrict__ b,
                               __nv_bfloat16* __restrict__ o, int total4)
{
    int i = blockIdx.x * blockDim.x + threadIdx.x;
    if (i >= total4) return;
    float4 va = ((const float4*)a)[i];
    float4 vb = ((const float4*)b)[i];
    uint2 hp;
    hp.x = ((uint32_t)b16(va.y + vb.y) << 16) | b16(va.x + vb.x);
    hp.y = ((uint32_t)b16(va.w + vb.w) << 16) | b16(va.z + vb.z);
    ((uint2*)o)[i] = hp;
}

// ---------------- q = cur + pos[:,3] -> single bf16 ----------------
__global__ void q_cvt_kernel(const float* __restrict__ cur, const float* __restrict__ pos,
                             __nv_bfloat16* __restrict__ o, int total4)
{
    int i = blockIdx.x * blockDim.x + threadIdx.x;
    if (i >= total4) return;
    int idx = i * 4;
    int n = idx / (LQ * D_MODEL);
    int rem = idx - n * (LQ * D_MODEL);
    float4 va = *(const float4*)(cur + idx);
    float4 vb = *(const float4*)(pos + (size_t)(n * N_LEVELS + 3) * (LQ * D_MODEL) + rem);
    uint2 hp;
    hp.x = ((uint32_t)b16(va.y + vb.y) << 16) | b16(va.x + vb.x);
    hp.y = ((uint32_t)b16(va.w + vb.w) << 16) | b16(va.z + vb.z);
    ((uint2*)o)[i] = hp;
}

// ---------------- 2-term bf16 HMMA GEMM ----------------
// C = epi( A @ (Bhi+Blo)^T + bias (,R) ); A single bf16, B pre-split hi/lo [N,K].
// CTA tile 128x128, BK=32, 2-stage cp.async double buffer, 8 warps (4m x 2n).
// EPI: 0=none 1=relu 2=+R 3=softmax16 (fp32 out).  OMODE: 0=fp32 C, 1=bf16 Cb.
#define SMPAD 40
#define MATW  (128 * SMPAD)
#define GEMM_SMEM_BYTES (2 * 3 * MATW * 2)   // 61440

template<int EPI, int OMODE>
__global__ void __launch_bounds__(256, 2) gemm2(
    const __nv_bfloat16* __restrict__ A,
    const __nv_bfloat16* __restrict__ Bhi, const __nv_bfloat16* __restrict__ Blo,
    const float* __restrict__ bias, const float* __restrict__ R,
    float* __restrict__ C, __nv_bfloat16* __restrict__ Cb,
    int M, int N, int K)
{
    extern __shared__ unsigned short sm[];
    const int tid = threadIdx.x;
    const int wid = tid >> 5, lane = tid & 31;
    const int wm = wid & 3, wn = wid >> 2;
    const int m0 = blockIdx.y * 128, n0 = blockIdx.x * 128;
    const uint32_t smb = smem_u32(sm);

    const int a_r  = lane & 15;
    const int a_kb = (lane >> 4) * 16;
    const int b_r  = ((lane >> 4) & 1) * 8 + (lane & 7);
    const int b_kb = ((lane >> 3) & 1) * 16;

    const int row_l = tid >> 2;          // 0..63
    const int q4    = tid & 3;

    float acc[2][8][4];
    #pragma unroll
    for (int i = 0; i < 2; i++)
        #pragma unroll
        for (int j = 0; j < 8; j++)
            #pragma unroll
            for (int t = 0; t < 4; t++) acc[i][j][t] = 0.f;

    const int nchunks = K >> 5;

    auto stage_load = [&](int buf, int k0) {
        #pragma unroll
        for (int j = 0; j < 6; j++) {
            const int mat = j >> 1;                     // 0 A, 1 Bh, 2 Bl
            const int row = (j & 1) * 64 + row_l;
            const __nv_bfloat16* base = (mat == 0) ? A : (mat == 1) ? Bhi : Blo;
            const int r0 = (mat == 0) ? m0 : n0;
            const __nv_bfloat16* src = base + (size_t)(r0 + row) * K + k0 + q4 * 8;
            const uint32_t dst = smb +
                (uint32_t)(((buf * 3 + mat) * MATW + row * SMPAD + q4 * 8) * 2);
            cp16(dst, src);
        }
        cp_commit();
    };

    stage_load(0, 0);
    for (int i = 0; i < nchunks; i++) {
        if (i + 1 < nchunks) { stage_load((i + 1) & 1, (i + 1) << 5); cp_wait<1>(); }
        else                 { cp_wait<0>(); }
        __syncthreads();

        const uint32_t sb  = smb + (uint32_t)((i & 1) * 3 * MATW * 2);
        const uint32_t AB  = sb;
        const uint32_t BhB = sb + MATW * 2, BlB = sb + 2 * MATW * 2;

        #pragma unroll
        for (int ks2 = 0; ks2 <= 32; ks2 += 32) {
            uint32_t ar[2][4];
            #pragma unroll
            for (int mi = 0; mi < 2; mi++) {
                const uint32_t ao = (uint32_t)((wm * 32 + mi * 16 + a_r) * (SMPAD * 2)) + a_kb + ks2;
                ldm_x4(ar[mi], AB + ao);
            }
            #pragma unroll
            for (int nc = 0; nc < 4; nc++) {
                uint32_t bh[4], bl[4];
                const uint32_t bo = (uint32_t)((wn * 64 + nc * 16 + b_r) * (SMPAD * 2)) + b_kb + ks2;
                ldm_x4(bh, BhB + bo);
                ldm_x4(bl, BlB + bo);
                #pragma unroll
                for (int mi = 0; mi < 2; mi++) {
                    #pragma unroll
                    for (int s = 0; s < 2; s++) {
                        float* c = acc[mi][nc * 2 + s];
                        mma_bf16(c, ar[mi], bh + s * 2);
                        mma_bf16(c, ar[mi], bl + s * 2);
                    }
                }
            }
        }
        __syncthreads();
    }

    // ---- epilogue ----
    const int gr = lane >> 2, gc = (lane & 3) * 2;

    if (EPI == 3) {
        // fused bias + softmax over groups of 16 columns; fp32 output.
        // group g covers cols wn*64 + g*16 .. +15 = ni pair (2g, 2g+1).
        // the 16 values of (row, group) live in the 4 quad lanes (shfl 1,2).
        #pragma unroll
        for (int mi = 0; mi < 2; mi++) {
            #pragma unroll
            for (int hrow = 0; hrow < 2; hrow++) {
                const int row = m0 + wm * 32 + mi * 16 + gr + hrow * 8;
                #pragma unroll
                for (int g = 0; g < 4; g++) {
                    const int c0 = n0 + wn * 64 + g * 16;
                    float a0 = acc[mi][2*g  ][2*hrow + 0] + bias[c0 + gc];
                    float a1 = acc[mi][2*g  ][2*hrow + 1] + bias[c0 + gc + 1];
                    float b0 = acc[mi][2*g+1][2*hrow + 0] + bias[c0 + 8 + gc];
                    float b1 = acc[mi][2*g+1][2*hrow + 1] + bias[c0 + 8 + gc + 1];
                    float mx = fmaxf(fmaxf(a0, a1), fmaxf(b0, b1));
                    mx = fmaxf(mx, __shfl_xor_sync(0xffffffffu, mx, 1));
                    mx = fmaxf(mx, __shfl_xor_sync(0xffffffffu, mx, 2));
                    a0 = __expf(a0 - mx); a1 = __expf(a1 - mx);
                    b0 = __expf(b0 - mx); b1 = __expf(b1 - mx);
                    float s = a0 + a1 + b0 + b1;
                    s += __shfl_xor_sync(0xffffffffu, s, 1);
                    s += __shfl_xor_sync(0xffffffffu, s, 2);
                    const float inv = 1.f / s;
                    *(float2*)(C + (size_t)row * N + c0 + gc)     = make_float2(a0 * inv, a1 * inv);
                    *(float2*)(C + (size_t)row * N + c0 + 8 + gc) = make_float2(b0 * inv, b1 * inv);
                }
            }
        }
        return;
    }

    #pragma unroll
    for (int mi = 0; mi < 2; mi++) {
        const int row = m0 + wm * 32 + mi * 16 + gr;
        #pragma unroll
        for (int ni = 0; ni < 8; ni++) {
            const int col = n0 + wn * 64 + ni * 8 + gc;
            const float b0 = bias[col], b1 = bias[col + 1];
            float2 v0, v1;
            v0.x = acc[mi][ni][0] + b0; v0.y = acc[mi][ni][1] + b1;
            v1.x = acc[mi][ni][2] + b0; v1.y = acc[mi][ni][3] + b1;
            if (EPI == 1) {
                v0.x = fmaxf(v0.x, 0.f); v0.y = fmaxf(v0.y, 0.f);
                v1.x = fmaxf(v1.x, 0.f); v1.y = fmaxf(v1.y, 0.f);
            }
            if (EPI == 2) {
                float2 r0 = *(const float2*)(R + (size_t)row * N + col);
                float2 r1 = *(const float2*)(R + (size_t)(row + 8) * N + col);
                v0.x += r0.x; v0.y += r0.y; v1.x += r1.x; v1.y += r1.y;
            }
            if (OMODE == 1) {
                *(uint32_t*)(Cb + (size_t)row * N + col) =
                    ((uint32_t)b16(v0.y) << 16) | b16(v0.x);
                *(uint32_t*)(Cb + (size_t)(row + 8) * N + col) =
                    ((uint32_t)b16(v1.y) << 16) | b16(v1.x);
            } else {
                *(float2*)(C + (size_t)row * N + col) = v0;
                *(float2*)(C + (size_t)(row + 8) * N + col) = v1;
            }
        }
    }
}

// ---------------- deformable gather, vectorized ----------------
// warp = (q, h). lane: half = lane>>4 selects x-corner (x0 / x0+1),
// pl = lane&15 covers dims {2pl, 2pl+1} via one uint32 (bf16x2) load.
// Per point: 2 warp-wide LDG.32 (y0 row, y1 row) cover all 4 corners.
// Final shfl_xor(16) merges the two x-corners; half 0 stores packed bf16x2.
__global__ void __launch_bounds__(256) deform_kernel(
    const __nv_bfloat16* __restrict__ value,
    const float* __restrict__ off,
    const float* __restrict__ attnw,
    const float* __restrict__ ref,
    __nv_bfloat16* __restrict__ outb)
{
    const int q = blockIdx.x;
    const int n = q >> 14;
    const int h = threadIdx.x >> 5;
    const int lane = threadIdx.x & 31;
    const int half = lane >> 4;
    const int pl = lane & 15;

    const float* offp = off   + (size_t)q * 256 + h * 32;
    const float* awp  = attnw + (size_t)q * 128 + h * 16;
    const float* refp = ref   + (size_t)q * 8;

    float2 acc = make_float2(0.f, 0.f);
    #pragma unroll
    for (int l = 0; l < N_LEVELS; l++) {
        const float rx = refp[l * 2 + 0] * 128.f - 0.5f;
        const float ry = refp[l * 2 + 1] * 128.f - 0.5f;
        const __nv_bfloat16* vb =
            value + (((size_t)n * LIN + l * LQ) * N_HEADS + h) * HEAD_DIM + 2 * pl;
        #pragma unroll
        for (int p = 0; p < N_POINTS; p++) {
            const float x = rx + offp[l * 8 + p * 2 + 0];
            const float y = ry + offp[l * 8 + p * 2 + 1];
            const float aw = awp[l * 4 + p];
            const float xf = floorf(x), yf = floorf(y);
            const int x0 = (int)xf, y0 = (int)yf;
            const float wx = x - xf, wy = y - yf;

            const int xs = x0 + half;                      // this half's x corner
            const float wxa = (half ? wx : 1.f - wx) * aw;
            const bool xok = (xs >= 0) && (xs < HW);
            const int xc = min(max(xs, 0), HW - 1);

            // y0 row
            {
                const float w = (xok && y0 >= 0 && y0 < HW) ? wxa * (1.f - wy) : 0.f;
                const int yc = min(max(y0, 0), HW - 1);
                const uint32_t u = *(const uint32_t*)(vb + (size_t)(yc * HW + xc) * 256);
                acc.x = fmaf(w, __uint_as_float(u << 16), acc.x);
                acc.y = fmaf(w, __uint_as_float(u & 0xffff0000u), acc.y);
            }
            // y1 row
            {
                const int y1 = y0 + 1;
                const float w = (xok && y1 >= 0 && y1 < HW) ? wxa * wy : 0.f;
                const int yc = min(max(y1, 0), HW - 1);
                const uint32_t u = *(const uint32_t*)(vb + (size_t)(yc * HW + xc) * 256);
                acc.x = fmaf(w, __uint_as_float(u << 16), acc.x);
                acc.y = fmaf(w, __uint_as_float(u & 0xffff0000u), acc.y);
            }
        }
    }
    acc.x += __shfl_xor_sync(0xffffffffu, acc.x, 16);
    acc.y += __shfl_xor_sync(0xffffffffu, acc.y, 16);
    if (half == 0) {
        *(uint32_t*)(outb + (size_t)q * 256 + h * 32 + 2 * pl) =
            ((uint32_t)b16(acc.y) << 16) | b16(acc.x);
    }
}

// ---------------- layernorm (optional single-bf16 copy) ----------------
template<bool OB>
__global__ void __launch_bounds__(256) layernorm_kernel(
    const float* __restrict__ X, const float* __restrict__ gamma,
    const float* __restrict__ beta, float* __restrict__ Y,
    __nv_bfloat16* __restrict__ Yb, int M)
{
    const int warp = threadIdx.x >> 5;
    const int lane = threadIdx.x & 31;
    const int row = blockIdx.x * 8 + warp;
    if (row >= M) return;

    const float* x = X + (size_t)row * D_MODEL + lane * 8;
    float4 v0 = *(const float4*)(x);
    float4 v1 = *(const float4*)(x + 4);

    float s  = v0.x + v0.y + v0.z + v0.w + v1.x + v1.y + v1.z + v1.w;
    float ss = v0.x*v0.x + v0.y*v0.y + v0.z*v0.z + v0.w*v0.w
             + v1.x*v1.x + v1.y*v1.y + v1.z*v1.z + v1.w*v1.w;
    #pragma unroll
    for (int o = 16; o > 0; o >>= 1) {
        s  += __shfl_xor_sync(0xffffffffu, s,  o);
        ss += __shfl_xor_sync(0xffffffffu, ss, o);
    }
    const float mean = s * (1.f / D_MODEL);
    const float var  = ss * (1.f / D_MODEL) - mean * mean;
    const float rstd = rsqrtf(var + LN_EPS);

    float4 g0 = *(const float4*)(gamma + lane * 8);
    float4 g1 = *(const float4*)(gamma + lane * 8 + 4);
    float4 b0 = *(const float4*)(beta + lane * 8);
    float4 b1 = *(const float4*)(beta + lane * 8 + 4);

    float4 o0, o1;
    o0.x = (v0.x - mean) * rstd * g0.x + b0.x;
    o0.y = (v0.y - mean) * rstd * g0.y + b0.y;
    o0.z = (v0.z - mean) * rstd * g0.z + b0.z;
    o0.w = (v0.w - mean) * rstd * g0.w + b0.w;
    o1.x = (v1.x - mean) * rstd * g1.x + b1.x;
    o1.y = (v1.y - mean) * rstd * g1.y + b1.y;
    o1.z = (v1.z - mean) * rstd * g1.z + b1.z;
    o1.w = (v1.w - mean) * rstd * g1.w + b1.w;

    float* y = Y + (size_t)row * D_MODEL + lane * 8;
    *(float4*)(y)     = o0;
    *(float4*)(y + 4) = o1;

    if (OB) {
        uint4 hp;
        hp.x = ((uint32_t)b16(o0.y) << 16) | b16(o0.x);
        hp.y = ((uint32_t)b16(o0.w) << 16) | b16(o0.z);
        hp.z = ((uint32_t)b16(o1.y) << 16) | b16(o1.x);
        hp.w = ((uint32_t)b16(o1.w) << 16) | b16(o1.z);
        *(uint4*)(Yb + (size_t)row * D_MODEL + lane * 8) = hp;
    }
}

// ---------------- launch ----------------
extern "C" void kernel_launch(void* const* d_in, const int* in_sizes, int n_in,
                              void* d_out, int out_size)
{
    const float* cur_src = (const float*)d_in[0];
    const float* src_all = (const float*)d_in[1];
    const float* pos     = (const float*)d_in[2];
    const float* ref     = (const float*)d_in[3];
    const float* W_off   = (const float*)d_in[6];
    const float* b_off   = (const float*)d_in[7];
    const float* W_attn  = (const float*)d_in[8];
    const float* b_attn  = (const float*)d_in[9];
    const float* W_val   = (const float*)d_in[10];
    const float* b_val   = (const float*)d_in[11];
    const float* W_out   = (const float*)d_in[12];
    const float* b_out   = (const float*)d_in[13];
    const float* gamma1  = (const float*)d_in[14];
    const float* beta1   = (const float*)d_in[15];
    const float* W1      = (const float*)d_in[16];
    const float* b1      = (const float*)d_in[17];
    const float* W2      = (const float*)d_in[18];
    const float* b2      = (const float*)d_in[19];
    const float* gamma2  = (const float*)d_in[20];
    const float* beta2   = (const float*)d_in[21];
    float* out = (float*)d_out;

    float* scratch = nullptr;
    cudaGetSymbolAddress((void**)&scratch, g_scratch);
    float* offb = scratch + OFF_OFFB;
    float* attn = scratch + OFF_ATTN;
    float* tmp  = scratch + OFF_TMP;
    float* src  = scratch + OFF_SRC;

    __nv_bfloat16* VAB = (__nv_bfloat16*)(scratch + OFF_VAB);
    __nv_bfloat16* VALB= (__nv_bfloat16*)(scratch + OFF_VALUEB);
    __nv_bfloat16* QB  = (__nv_bfloat16*)(scratch + OFF_QB);
    __nv_bfloat16* AOB = (__nv_bfloat16*)(scratch + OFF_AOB);
    __nv_bfloat16* SRCB= (__nv_bfloat16*)(scratch + OFF_SRCB);
    __nv_bfloat16* HB  = (__nv_bfloat16*)(scratch + OFF_HB);
    __nv_bfloat16* WVH = (__nv_bfloat16*)(scratch + OFF_WVH);
    __nv_bfloat16* WVL = (__nv_bfloat16*)(scratch + OFF_WVL);
    __nv_bfloat16* WOH = (__nv_bfloat16*)(scratch + OFF_WOH);
    __nv_bfloat16* WOL = (__nv_bfloat16*)(scratch + OFF_WOL);
    __nv_bfloat16* WAH = (__nv_bfloat16*)(scratch + OFF_WAH);
    __nv_bfloat16* WAL = (__nv_bfloat16*)(scratch + OFF_WAL);
    __nv_bfloat16* WUH = (__nv_bfloat16*)(scratch + OFF_WUH);
    __nv_bfloat16* WUL = (__nv_bfloat16*)(scratch + OFF_WUL);
    __nv_bfloat16* W1H = (__nv_bfloat16*)(scratch + OFF_W1H);
    __nv_bfloat16* W1L = (__nv_bfloat16*)(scratch + OFF_W1L);
    __nv_bfloat16* W2H = (__nv_bfloat16*)(scratch + OFF_W2H);
    __nv_bfloat16* W2L = (__nv_bfloat16*)(scratch + OFF_W2L);

    cudaFuncSetAttribute((const void*)gemm2<0, 0>,
                         cudaFuncAttributeMaxDynamicSharedMemorySize, GEMM_SMEM_BYTES);
    cudaFuncSetAttribute((const void*)gemm2<0, 1>,
                         cudaFuncAttributeMaxDynamicSharedMemorySize, GEMM_SMEM_BYTES);
    cudaFuncSetAttribute((const void*)gemm2<1, 1>,
                         cudaFuncAttributeMaxDynamicSharedMemorySize, GEMM_SMEM_BYTES);
    cudaFuncSetAttribute((const void*)gemm2<2, 0>,
                         cudaFuncAttributeMaxDynamicSharedMemorySize, GEMM_SMEM_BYTES);
    cudaFuncSetAttribute((const void*)gemm2<3, 0>,
                         cudaFuncAttributeMaxDynamicSharedMemorySize, GEMM_SMEM_BYTES);

    // 0. merged weight transpose + split (1 launch)
    {
        WSJobs j;
        j.src[0] = W_val;  j.hi[0] = WVH; j.lo[0] = WVL; j.K[0] = 256;  j.N[0] = 256;
        j.src[1] = W_off;  j.hi[1] = WOH; j.lo[1] = WOL; j.K[1] = 256;  j.N[1] = 256;
        j.src[2] = W_attn; j.hi[2] = WAH; j.lo[2] = WAL; j.K[2] = 256;  j.N[2] = 128;
        j.src[3] = W_out;  j.hi[3] = WUH; j.lo[3] = WUL; j.K[3] = 256;  j.N[3] = 256;
        j.src[4] = W1;     j.hi[4] = W1H; j.lo[4] = W1L; j.K[4] = 256;  j.N[4] = 1024;
        j.src[5] = W2;     j.hi[5] = W2H; j.lo[5] = W2L; j.K[5] = 1024; j.N[5] = 256;
        int off = 0;
        for (int s = 0; s < 6; s++) { j.off[s] = off; off += j.K[s] * j.N[s]; }
        j.off[6] = off;
        wsplit_all_kernel<<<(off + 255) / 256, 256>>>(j);
    }

    // 0b. activation converts
    add_cvt_kernel<<<(M_V*64 + 255)/256, 256>>>(src_all, pos, VAB, M_V * 64);
    q_cvt_kernel<<<(M_Q*64 + 255)/256, 256>>>(cur_src, pos, QB, M_Q * 64);

    // 1. value = (src_all + pos) @ W_val + b_val  -> bf16
    {
        dim3 grid(2, M_V / 128);
        gemm2<0, 1><<<grid, 256, GEMM_SMEM_BYTES>>>(
            VAB, WVH, WVL, b_val, nullptr, nullptr, VALB, M_V, 256, 256);
    }

    // 2. off = q @ W_off + b_off  -> fp32
    {
        dim3 grid(2, M_Q / 128);
        gemm2<0, 0><<<grid, 256, GEMM_SMEM_BYTES>>>(
            QB, WOH, WOL, b_off, nullptr, offb, nullptr, M_Q, 256, 256);
    }

    // 3. attn = softmax16( q @ W_attn + b_attn ), fused epilogue
    {
        dim3 grid(1, M_Q / 128);
        gemm2<3, 0><<<grid, 256, GEMM_SMEM_BYTES>>>(
            QB, WAH, WAL, b_attn, nullptr, attn, nullptr, M_Q, 128, 256);
    }

    // 4. deformable gather -> bf16 attnout
    deform_kernel<<<M_Q, 256>>>(VALB, offb, attn, ref, AOB);

    // 5. tmp = attnout @ W_out + b_out + cur_src ; src = LN1(tmp) (+ bf16 copy)
    {
        dim3 grid(2, M_Q / 128);
        gemm2<2, 0><<<grid, 256, GEMM_SMEM_BYTES>>>(
            AOB, WUH, WUL, b_out, cur_src, tmp, nullptr, M_Q, 256, 256);
        layernorm_kernel<true><<<(M_Q + 7) / 8, 256>>>(tmp, gamma1, beta1, src, SRCB, M_Q);
    }

    // 6. h = relu(src @ W1 + b1) -> bf16
    {
        dim3 grid(8, M_Q / 128);
        gemm2<1, 1><<<grid, 256, GEMM_SMEM_BYTES>>>(
            SRCB, W1H, W1L, b1, nullptr, nullptr, HB, M_Q, D_FFN, 256);
    }

    // 7. tmp = h @ W2 + b2 + src ; out = LN2(tmp)
    {
        dim3 grid(2, M_Q / 128);
        gemm2<2, 0><<<grid, 256, GEMM_SMEM_BYTES>>>(
            HB, W2H, W2L, b2, src, tmp, nullptr, M_Q, 256, D_FFN);
        layernorm_kernel<false><<<(M_Q + 7) / 8, 256>>>(tmp, gamma2, beta2, out, nullptr, M_Q);
    }
}

// round 11
// speedup vs baseline: 3.1325x; 1.2433x over previous
#include <cuda_runtime.h>
#include <cuda_bf16.h>
#include <cstdint>
#include <math.h>

// ---------------- problem constants ----------------
#define BATCH     2
#define HW        128
#define LQ        (HW*HW)          // 16384
#define N_LEVELS  4
#define LIN       (N_LEVELS*LQ)    // 65536
#define D_MODEL   256
#define N_HEADS   8
#define HEAD_DIM  32
#define N_POINTS  4
#define D_FFN     1024
#define LN_EPS    1e-5f

#define M_Q   (BATCH*LQ)           // 32768
#define M_V   (BATCH*LIN)          // 131072

// ---------------- scratch layout (in floats) ----------------
#define OFF_VAB     0            // (src_all+pos) bf16   M_V*256
#define OFF_VALUEB  16777216     // value bf16           M_V*256
#define OFF_QB      33554432     // q bf16               M_Q*256
#define OFF_OFFB    37748736     // off fp32             M_Q*256
#define OFF_ATTN    46137344     // attn fp32            M_Q*128
#define OFF_AOB     50331648     // attnout bf16         M_Q*256
#define OFF_TMP     54525952     // fp32                 M_Q*256
#define OFF_SRC     62914560     // fp32                 M_Q*256
#define OFF_SRCB    71303168     // src bf16             M_Q*256
#define OFF_HB      75497472     // h bf16               M_Q*1024
#define OFF_WVH     92274688
#define OFF_WVL     92307456
#define OFF_WOH     92340224
#define OFF_WOL     92372992
#define OFF_WAH     92405760
#define OFF_WAL     92422144
#define OFF_WUH     92438528
#define OFF_WUL     92471296
#define OFF_W1H     92504064
#define OFF_W1L     92635136
#define OFF_W2H     92766208
#define OFF_W2L     92897280
#define SCRATCH_FLOATS 93028352

__device__ float g_scratch[SCRATCH_FLOATS];

// ---------------- helpers ----------------
__device__ __forceinline__ uint32_t smem_u32(const void* p) {
    uint32_t a;
    asm("{ .reg .u64 t; cvta.to.shared.u64 t, %1; cvt.u32.u64 %0, t; }" : "=r"(a) : "l"(p));
    return a;
}

__device__ __forceinline__ unsigned short b16(float x) {
    return __bfloat16_as_ushort(__float2bfloat16_rn(x));
}

__device__ __forceinline__ void ldm_x4(uint32_t* r, uint32_t addr) {
    asm volatile("ldmatrix.sync.aligned.m8n8.x4.shared.b16 {%0,%1,%2,%3}, [%4];"
        : "=r"(r[0]), "=r"(r[1]), "=r"(r[2]), "=r"(r[3]) : "r"(addr));
}

__device__ __forceinline__ void mma_bf16(float* c, const uint32_t* a, const uint32_t* b) {
    asm volatile(
        "mma.sync.aligned.m16n8k16.row.col.f32.bf16.bf16.f32 "
        "{%0,%1,%2,%3}, {%4,%5,%6,%7}, {%8,%9}, {%0,%1,%2,%3};"
        : "+f"(c[0]), "+f"(c[1]), "+f"(c[2]), "+f"(c[3])
        : "r"(a[0]), "r"(a[1]), "r"(a[2]), "r"(a[3]), "r"(b[0]), "r"(b[1]));
}

__device__ __forceinline__ void cp16(uint32_t dst, const void* src) {
    asm volatile("cp.async.cg.shared.global [%0], [%1], 16;" :: "r"(dst), "l"(src));
}
__device__ __forceinline__ void cp_commit() { asm volatile("cp.async.commit_group;"); }
template<int W> __device__ __forceinline__ void cp_wait() {
    asm volatile("cp.async.wait_group %0;" :: "n"(W));
}

// ---------------- merged weight transpose + bf16 hi/lo split ----------------
struct WSJobs {
    const float* src[6];
    __nv_bfloat16* hi[6];
    __nv_bfloat16* lo[6];
    int K[6];
    int N[6];
    int off[7];
};

__global__ void wsplit_all_kernel(WSJobs jobs)
{
    int idx = blockIdx.x * blockDim.x + threadIdx.x;
    if (idx >= jobs.off[6]) return;
    #pragma unroll
    for (int s = 0; s < 6; s++) {
        if (idx >= jobs.off[s] && idx < jobs.off[s + 1]) {
            int local = idx - jobs.off[s];
            int N = jobs.N[s], K = jobs.K[s];
            int k = local / N, n = local - k * N;
            float x = jobs.src[s][local];
            __nv_bfloat16 h = __float2bfloat16_rn(x);
            __nv_bfloat16 l = __float2bfloat16_rn(x - __bfloat162float(h));
            jobs.hi[s][(size_t)n * K + k] = h;
            jobs.lo[s][(size_t)n * K + k] = l;
            return;
        }
    }
}

// ---------------- elementwise add -> single bf16 ----------------
__global__ void add_cvt_kernel(const float* __restrict__ a, const float* __restrict__ b,
                               __nv_bfloat16* __restrict__ o, int total4)
{
    int i = blockIdx.x * blockDim.x + threadIdx.x;
    if (i >= total4) return;
    float4 va = ((const float4*)a)[i];
    float4 vb = ((const float4*)b)[i];
    uint2 hp;
    hp.x = ((uint32_t)b16(va.y + vb.y) << 16) | b16(va.x + vb.x);
    hp.y = ((uint32_t)b16(va.w + vb.w) << 16) | b16(va.z + vb.z);
    ((uint2*)o)[i] = hp;
}

// ---------------- q = cur + pos[:,3] -> single bf16 ----------------
__global__ void q_cvt_kernel(const float* __restrict__ cur, const float* __restrict__ pos,
                             __nv_bfloat16* __restrict__ o, int total4)
{
    int i = blockIdx.x * blockDim.x + threadIdx.x;
    if (i >= total4) return;
    int idx = i * 4;
    int n = idx / (LQ * D_MODEL);
    int rem = idx - n * (LQ * D_MODEL);
    float4 va = *(const float4*)(cur + idx);
    float4 vb = *(const float4*)(pos + (size_t)(n * N_LEVELS + 3) * (LQ * D_MODEL) + rem);
    uint2 hp;
    hp.x = ((uint32_t)b16(va.y + vb.y) << 16) | b16(va.x + vb.x);
    hp.y = ((uint32_t)b16(va.w + vb.w) << 16) | b16(va.z + vb.z);
    ((uint2*)o)[i] = hp;
}

// ---------------- bf16 HMMA GEMM (optional B hi/lo split) ----------------
// C = epi( A @ B^T + bias (,R) ); A single bf16; B either single (BSPLIT=0)
// or pre-split hi/lo (BSPLIT=1), [N,K] K-major.
// CTA tile 128x128, BK=32, 2-stage cp.async double buffer, 8 warps (4m x 2n).
// EPI: 0=none 1=relu 2=+R 3=softmax16 (fp32 out).  OMODE: 0=fp32 C, 1=bf16 Cb.
#define SMPAD 40
#define MATW  (128 * SMPAD)

template<int EPI, int OMODE, int BSPLIT>
__global__ void __launch_bounds__(256, 2) gemm2(
    const __nv_bfloat16* __restrict__ A,
    const __nv_bfloat16* __restrict__ Bhi, const __nv_bfloat16* __restrict__ Blo,
    const float* __restrict__ bias, const float* __restrict__ R,
    float* __restrict__ C, __nv_bfloat16* __restrict__ Cb,
    int M, int N, int K)
{
    const int NMAT = BSPLIT ? 3 : 2;
    extern __shared__ unsigned short sm[];
    const int tid = threadIdx.x;
    const int wid = tid >> 5, lane = tid & 31;
    const int wm = wid & 3, wn = wid >> 2;
    const int m0 = blockIdx.y * 128, n0 = blockIdx.x * 128;
    const uint32_t smb = smem_u32(sm);

    const int a_r  = lane & 15;
    const int a_kb = (lane >> 4) * 16;
    const int b_r  = ((lane >> 4) & 1) * 8 + (lane & 7);
    const int b_kb = ((lane >> 3) & 1) * 16;

    const int row_l = tid >> 2;          // 0..63
    const int q4    = tid & 3;

    float acc[2][8][4];
    #pragma unroll
    for (int i = 0; i < 2; i++)
        #pragma unroll
        for (int j = 0; j < 8; j++)
            #pragma unroll
            for (int t = 0; t < 4; t++) acc[i][j][t] = 0.f;

    const int nchunks = K >> 5;

    auto stage_load = [&](int buf, int k0) {
        #pragma unroll
        for (int j = 0; j < 2 * NMAT; j++) {
            const int mat = j >> 1;                     // 0 A, 1 Bh, (2 Bl)
            const int row = (j & 1) * 64 + row_l;
            const __nv_bfloat16* base = (mat == 0) ? A : (mat == 1) ? Bhi : Blo;
            const int r0 = (mat == 0) ? m0 : n0;
            const __nv_bfloat16* src = base + (size_t)(r0 + row) * K + k0 + q4 * 8;
            const uint32_t dst = smb +
                (uint32_t)(((buf * NMAT + mat) * MATW + row * SMPAD + q4 * 8) * 2);
            cp16(dst, src);
        }
        cp_commit();
    };

    stage_load(0, 0);
    for (int i = 0; i < nchunks; i++) {
        if (i + 1 < nchunks) { stage_load((i + 1) & 1, (i + 1) << 5); cp_wait<1>(); }
        else                 { cp_wait<0>(); }
        __syncthreads();

        const uint32_t sb  = smb + (uint32_t)((i & 1) * NMAT * MATW * 2);
        const uint32_t AB  = sb;
        const uint32_t BhB = sb + MATW * 2, BlB = sb + 2 * MATW * 2;

        #pragma unroll
        for (int ks2 = 0; ks2 <= 32; ks2 += 32) {
            uint32_t ar[2][4];
            #pragma unroll
            for (int mi = 0; mi < 2; mi++) {
                const uint32_t ao = (uint32_t)((wm * 32 + mi * 16 + a_r) * (SMPAD * 2)) + a_kb + ks2;
                ldm_x4(ar[mi], AB + ao);
            }
            #pragma unroll
            for (int nc = 0; nc < 4; nc++) {
                uint32_t bh[4], bl[4];
                const uint32_t bo = (uint32_t)((wn * 64 + nc * 16 + b_r) * (SMPAD * 2)) + b_kb + ks2;
                ldm_x4(bh, BhB + bo);
                if (BSPLIT) ldm_x4(bl, BlB + bo);
                #pragma unroll
                for (int mi = 0; mi < 2; mi++) {
                    #pragma unroll
                    for (int s = 0; s < 2; s++) {
                        float* c = acc[mi][nc * 2 + s];
                        mma_bf16(c, ar[mi], bh + s * 2);
                        if (BSPLIT) mma_bf16(c, ar[mi], bl + s * 2);
                    }
                }
            }
        }
        __syncthreads();
    }

    // ---- epilogue ----
    const int gr = lane >> 2, gc = (lane & 3) * 2;

    if (EPI == 3) {
        // fused bias + softmax over groups of 16 columns; fp32 output.
        #pragma unroll
        for (int mi = 0; mi < 2; mi++) {
            #pragma unroll
            for (int hrow = 0; hrow < 2; hrow++) {
                const int row = m0 + wm * 32 + mi * 16 + gr + hrow * 8;
                #pragma unroll
                for (int g = 0; g < 4; g++) {
                    const int c0 = n0 + wn * 64 + g * 16;
                    float a0 = acc[mi][2*g  ][2*hrow + 0] + bias[c0 + gc];
                    float a1 = acc[mi][2*g  ][2*hrow + 1] + bias[c0 + gc + 1];
                    float b0 = acc[mi][2*g+1][2*hrow + 0] + bias[c0 + 8 + gc];
                    float b1 = acc[mi][2*g+1][2*hrow + 1] + bias[c0 + 8 + gc + 1];
                    float mx = fmaxf(fmaxf(a0, a1), fmaxf(b0, b1));
                    mx = fmaxf(mx, __shfl_xor_sync(0xffffffffu, mx, 1));
                    mx = fmaxf(mx, __shfl_xor_sync(0xffffffffu, mx, 2));
                    a0 = __expf(a0 - mx); a1 = __expf(a1 - mx);
                    b0 = __expf(b0 - mx); b1 = __expf(b1 - mx);
                    float s = a0 + a1 + b0 + b1;
                    s += __shfl_xor_sync(0xffffffffu, s, 1);
                    s += __shfl_xor_sync(0xffffffffu, s, 2);
                    const float inv = 1.f / s;
                    *(float2*)(C + (size_t)row * N + c0 + gc)     = make_float2(a0 * inv, a1 * inv);
                    *(float2*)(C + (size_t)row * N + c0 + 8 + gc) = make_float2(b0 * inv, b1 * inv);
                }
            }
        }
        return;
    }

    #pragma unroll
    for (int mi = 0; mi < 2; mi++) {
        const int row = m0 + wm * 32 + mi * 16 + gr;
        #pragma unroll
        for (int ni = 0; ni < 8; ni++) {
            const int col = n0 + wn * 64 + ni * 8 + gc;
            const float b0 = bias[col], b1 = bias[col + 1];
            float2 v0, v1;
            v0.x = acc[mi][ni][0] + b0; v0.y = acc[mi][ni][1] + b1;
            v1.x = acc[mi][ni][2] + b0; v1.y = acc[mi][ni][3] + b1;
            if (EPI == 1) {
                v0.x = fmaxf(v0.x, 0.f); v0.y = fmaxf(v0.y, 0.f);
                v1.x = fmaxf(v1.x, 0.f); v1.y = fmaxf(v1.y, 0.f);
            }
            if (EPI == 2) {
                float2 r0 = *(const float2*)(R + (size_t)row * N + col);
                float2 r1 = *(const float2*)(R + (size_t)(row + 8) * N + col);
                v0.x += r0.x; v0.y += r0.y; v1.x += r1.x; v1.y += r1.y;
            }
            if (OMODE == 1) {
                *(uint32_t*)(Cb + (size_t)row * N + col) =
                    ((uint32_t)b16(v0.y) << 16) | b16(v0.x);
                *(uint32_t*)(Cb + (size_t)(row + 8) * N + col) =
                    ((uint32_t)b16(v1.y) << 16) | b16(v1.x);
            } else {
                *(float2*)(C + (size_t)row * N + col) = v0;
                *(float2*)(C + (size_t)(row + 8) * N + col) = v1;
            }
        }
    }
}

// ---------------- deformable gather, vectorized ----------------
__global__ void __launch_bounds__(256) deform_kernel(
    const __nv_bfloat16* __restrict__ value,
    const float* __restrict__ off,
    const float* __restrict__ attnw,
    const float* __restrict__ ref,
    __nv_bfloat16* __restrict__ outb)
{
    const int q = blockIdx.x;
    const int n = q >> 14;
    const int h = threadIdx.x >> 5;
    const int lane = threadIdx.x & 31;
    const int half = lane >> 4;
    const int pl = lane & 15;

    const float* offp = off   + (size_t)q * 256 + h * 32;
    const float* awp  = attnw + (size_t)q * 128 + h * 16;
    const float* refp = ref   + (size_t)q * 8;

    float2 acc = make_float2(0.f, 0.f);
    #pragma unroll
    for (int l = 0; l < N_LEVELS; l++) {
        const float rx = refp[l * 2 + 0] * 128.f - 0.5f;
        const float ry = refp[l * 2 + 1] * 128.f - 0.5f;
        const __nv_bfloat16* vb =
            value + (((size_t)n * LIN + l * LQ) * N_HEADS + h) * HEAD_DIM + 2 * pl;
        #pragma unroll
        for (int p = 0; p < N_POINTS; p++) {
            const float x = rx + offp[l * 8 + p * 2 + 0];
            const float y = ry + offp[l * 8 + p * 2 + 1];
            const float aw = awp[l * 4 + p];
            const float xf = floorf(x), yf = floorf(y);
            const int x0 = (int)xf, y0 = (int)yf;
            const float wx = x - xf, wy = y - yf;

            const int xs = x0 + half;
            const float wxa = (half ? wx : 1.f - wx) * aw;
            const bool xok = (xs >= 0) && (xs < HW);
            const int xc = min(max(xs, 0), HW - 1);

            {
                const float w = (xok && y0 >= 0 && y0 < HW) ? wxa * (1.f - wy) : 0.f;
                const int yc = min(max(y0, 0), HW - 1);
                const uint32_t u = *(const uint32_t*)(vb + (size_t)(yc * HW + xc) * 256);
                acc.x = fmaf(w, __uint_as_float(u << 16), acc.x);
                acc.y = fmaf(w, __uint_as_float(u & 0xffff0000u), acc.y);
            }
            {
                const int y1 = y0 + 1;
                const float w = (xok && y1 >= 0 && y1 < HW) ? wxa * wy : 0.f;
                const int yc = min(max(y1, 0), HW - 1);
                const uint32_t u = *(const uint32_t*)(vb + (size_t)(yc * HW + xc) * 256);
                acc.x = fmaf(w, __uint_as_float(u << 16), acc.x);
                acc.y = fmaf(w, __uint_as_float(u & 0xffff0000u), acc.y);
            }
        }
    }
    acc.x += __shfl_xor_sync(0xffffffffu, acc.x, 16);
    acc.y += __shfl_xor_sync(0xffffffffu, acc.y, 16);
    if (half == 0) {
        *(uint32_t*)(outb + (size_t)q * 256 + h * 32 + 2 * pl) =
            ((uint32_t)b16(acc.y) << 16) | b16(acc.x);
    }
}

// ---------------- layernorm (optional single-bf16 copy) ----------------
template<bool OB>
__global__ void __launch_bounds__(256) layernorm_kernel(
    const float* __restrict__ X, const float* __restrict__ gamma,
    const float* __restrict__ beta, float* __restrict__ Y,
    __nv_bfloat16* __restrict__ Yb, int M)
{
    const int warp = threadIdx.x >> 5;
    const int lane = threadIdx.x & 31;
    const int row = blockIdx.x * 8 + warp;
    if (row >= M) return;

    const float* x = X + (size_t)row * D_MODEL + lane * 8;
    float4 v0 = *(const float4*)(x);
    float4 v1 = *(const float4*)(x + 4);

    float s  = v0.x + v0.y + v0.z + v0.w + v1.x + v1.y + v1.z + v1.w;
    float ss = v0.x*v0.x + v0.y*v0.y + v0.z*v0.z + v0.w*v0.w
             + v1.x*v1.x + v1.y*v1.y + v1.z*v1.z + v1.w*v1.w;
    #pragma unroll
    for (int o = 16; o > 0; o >>= 1) {
        s  += __shfl_xor_sync(0xffffffffu, s,  o);
        ss += __shfl_xor_sync(0xffffffffu, ss, o);
    }
    const float mean = s * (1.f / D_MODEL);
    const float var  = ss * (1.f / D_MODEL) - mean * mean;
    const float rstd = rsqrtf(var + LN_EPS);

    float4 g0 = *(const float4*)(gamma + lane * 8);
    float4 g1 = *(const float4*)(gamma + lane * 8 + 4);
    float4 b0 = *(const float4*)(beta + lane * 8);
    float4 b1 = *(const float4*)(beta + lane * 8 + 4);

    float4 o0, o1;
    o0.x = (v0.x - mean) * rstd * g0.x + b0.x;
    o0.y = (v0.y - mean) * rstd * g0.y + b0.y;
    o0.z = (v0.z - mean) * rstd * g0.z + b0.z;
    o0.w = (v0.w - mean) * rstd * g0.w + b0.w;
    o1.x = (v1.x - mean) * rstd * g1.x + b1.x;
    o1.y = (v1.y - mean) * rstd * g1.y + b1.y;
    o1.z = (v1.z - mean) * rstd * g1.z + b1.z;
    o1.w = (v1.w - mean) * rstd * g1.w + b1.w;

    float* y = Y + (size_t)row * D_MODEL + lane * 8;
    *(float4*)(y)     = o0;
    *(float4*)(y + 4) = o1;

    if (OB) {
        uint4 hp;
        hp.x = ((uint32_t)b16(o0.y) << 16) | b16(o0.x);
        hp.y = ((uint32_t)b16(o0.w) << 16) | b16(o0.z);
        hp.z = ((uint32_t)b16(o1.y) << 16) | b16(o1.x);
        hp.w = ((uint32_t)b16(o1.w) << 16) | b16(o1.z);
        *(uint4*)(Yb + (size_t)row * D_MODEL + lane * 8) = hp;
    }
}

// ---------------- launch ----------------
extern "C" void kernel_launch(void* const* d_in, const int* in_sizes, int n_in,
                              void* d_out, int out_size)
{
    const float* cur_src = (const float*)d_in[0];
    const float* src_all = (const float*)d_in[1];
    const float* pos     = (const float*)d_in[2];
    const float* ref     = (const float*)d_in[3];
    const float* W_off   = (const float*)d_in[6];
    const float* b_off   = (const float*)d_in[7];
    const float* W_attn  = (const float*)d_in[8];
    const float* b_attn  = (const float*)d_in[9];
    const float* W_val   = (const float*)d_in[10];
    const float* b_val   = (const float*)d_in[11];
    const float* W_out   = (const float*)d_in[12];
    const float* b_out   = (const float*)d_in[13];
    const float* gamma1  = (const float*)d_in[14];
    const float* beta1   = (const float*)d_in[15];
    const float* W1      = (const float*)d_in[16];
    const float* b1      = (const float*)d_in[17];
    const float* W2      = (const float*)d_in[18];
    const float* b2      = (const float*)d_in[19];
    const float* gamma2  = (const float*)d_in[20];
    const float* beta2   = (const float*)d_in[21];
    float* out = (float*)d_out;

    float* scratch = nullptr;
    cudaGetSymbolAddress((void**)&scratch, g_scratch);
    float* offb = scratch + OFF_OFFB;
    float* attn = scratch + OFF_ATTN;
    float* tmp  = scratch + OFF_TMP;
    float* src  = scratch + OFF_SRC;

    __nv_bfloat16* VAB = (__nv_bfloat16*)(scratch + OFF_VAB);
    __nv_bfloat16* VALB= (__nv_bfloat16*)(scratch + OFF_VALUEB);
    __nv_bfloat16* QB  = (__nv_bfloat16*)(scratch + OFF_QB);
    __nv_bfloat16* AOB = (__nv_bfloat16*)(scratch + OFF_AOB);
    __nv_bfloat16* SRCB= (__nv_bfloat16*)(scratch + OFF_SRCB);
    __nv_bfloat16* HB  = (__nv_bfloat16*)(scratch + OFF_HB);
    __nv_bfloat16* WVH = (__nv_bfloat16*)(scratch + OFF_WVH);
    __nv_bfloat16* WVL = (__nv_bfloat16*)(scratch + OFF_WVL);
    __nv_bfloat16* WOH = (__nv_bfloat16*)(scratch + OFF_WOH);
    __nv_bfloat16* WOL = (__nv_bfloat16*)(scratch + OFF_WOL);
    __nv_bfloat16* WAH = (__nv_bfloat16*)(scratch + OFF_WAH);
    __nv_bfloat16* WAL = (__nv_bfloat16*)(scratch + OFF_WAL);
    __nv_bfloat16* WUH = (__nv_bfloat16*)(scratch + OFF_WUH);
    __nv_bfloat16* WUL = (__nv_bfloat16*)(scratch + OFF_WUL);
    __nv_bfloat16* W1H = (__nv_bfloat16*)(scratch + OFF_W1H);
    __nv_bfloat16* W1L = (__nv_bfloat16*)(scratch + OFF_W1L);
    __nv_bfloat16* W2H = (__nv_bfloat16*)(scratch + OFF_W2H);
    __nv_bfloat16* W2L = (__nv_bfloat16*)(scratch + OFF_W2L);

    const int SMEM3 = 2 * 3 * MATW * 2;   // split-B stages
    const int SMEM2 = 2 * 2 * MATW * 2;   // single-B stages

    cudaFuncSetAttribute((const void*)gemm2<0, 0, 1>,
                         cudaFuncAttributeMaxDynamicSharedMemorySize, SMEM3);
    cudaFuncSetAttribute((const void*)gemm2<3, 0, 1>,
                         cudaFuncAttributeMaxDynamicSharedMemorySize, SMEM3);
    cudaFuncSetAttribute((const void*)gemm2<0, 1, 0>,
                         cudaFuncAttributeMaxDynamicSharedMemorySize, SMEM2);
    cudaFuncSetAttribute((const void*)gemm2<1, 1, 0>,
                         cudaFuncAttributeMaxDynamicSharedMemorySize, SMEM2);
    cudaFuncSetAttribute((const void*)gemm2<2, 0, 0>,
                         cudaFuncAttributeMaxDynamicSharedMemorySize, SMEM2);

    // 0. merged weight transpose + split (1 launch)
    {
        WSJobs j;
        j.src[0] = W_val;  j.hi[0] = WVH; j.lo[0] = WVL; j.K[0] = 256;  j.N[0] = 256;
        j.src[1] = W_off;  j.hi[1] = WOH; j.lo[1] = WOL; j.K[1] = 256;  j.N[1] = 256;
        j.src[2] = W_attn; j.hi[2] = WAH; j.lo[2] = WAL; j.K[2] = 256;  j.N[2] = 128;
        j.src[3] = W_out;  j.hi[3] = WUH; j.lo[3] = WUL; j.K[3] = 256;  j.N[3] = 256;
        j.src[4] = W1;     j.hi[4] = W1H; j.lo[4] = W1L; j.K[4] = 256;  j.N[4] = 1024;
        j.src[5] = W2;     j.hi[5] = W2H; j.lo[5] = W2L; j.K[5] = 1024; j.N[5] = 256;
        int off = 0;
        for (int s = 0; s < 6; s++) { j.off[s] = off; off += j.K[s] * j.N[s]; }
        j.off[6] = off;
        wsplit_all_kernel<<<(off + 255) / 256, 256>>>(j);
    }

    // 0b. activation converts
    add_cvt_kernel<<<(M_V*64 + 255)/256, 256>>>(src_all, pos, VAB, M_V * 64);
    q_cvt_kernel<<<(M_Q*64 + 255)/256, 256>>>(cur_src, pos, QB, M_Q * 64);

    // 1. value = (src_all + pos) @ W_val + b_val  -> bf16  (single-B)
    {
        dim3 grid(2, M_V / 128);
        gemm2<0, 1, 0><<<grid, 256, SMEM2>>>(
            VAB, WVH, nullptr, b_val, nullptr, nullptr, VALB, M_V, 256, 256);
    }

    // 2. off = q @ W_off + b_off  -> fp32  (split-B: position path)
    {
        dim3 grid(2, M_Q / 128);
        gemm2<0, 0, 1><<<grid, 256, SMEM3>>>(
            QB, WOH, WOL, b_off, nullptr, offb, nullptr, M_Q, 256, 256);
    }

    // 3. attn = softmax16( q @ W_attn + b_attn ), fused epilogue (split-B)
    {
        dim3 grid(1, M_Q / 128);
        gemm2<3, 0, 1><<<grid, 256, SMEM3>>>(
            QB, WAH, WAL, b_attn, nullptr, attn, nullptr, M_Q, 128, 256);
    }

    // 4. deformable gather -> bf16 attnout
    deform_kernel<<<M_Q, 256>>>(VALB, offb, attn, ref, AOB);

    // 5. tmp = attnout @ W_out + b_out + cur_src ; src = LN1(tmp) (+ bf16 copy)  (single-B)
    {
        dim3 grid(2, M_Q / 128);
        gemm2<2, 0, 0><<<grid, 256, SMEM2>>>(
            AOB, WUH, nullptr, b_out, cur_src, tmp, nullptr, M_Q, 256, 256);
        layernorm_kernel<true><<<(M_Q + 7) / 8, 256>>>(tmp, gamma1, beta1, src, SRCB, M_Q);
    }

    // 6. h = relu(src @ W1 + b1) -> bf16  (single-B)
    {
        dim3 grid(8, M_Q / 128);
        gemm2<1, 1, 0><<<grid, 256, SMEM2>>>(
            SRCB, W1H, nullptr, b1, nullptr, nullptr, HB, M_Q, D_FFN, 256);
    }

    // 7. tmp = h @ W2 + b2 + src ; out = LN2(tmp)  (single-B)
    {
        dim3 grid(2, M_Q / 128);
        gemm2<2, 0, 0><<<grid, 256, SMEM2>>>(
            HB, W2H, nullptr, b2, src, tmp, nullptr, M_Q, 256, D_FFN);
        layernorm_kernel<false><<<(M_Q + 7) / 8, 256>>>(tmp, gamma2, beta2, out, nullptr, M_Q);
    }
}